// round 12
// baseline (speedup 1.0000x reference)
#include <cuda_runtime.h>
#include <cuda_bf16.h>
#include <math.h>
#include <float.h>

#define NR 100
#define BB 16
#define FLATN 10000
#define G1_KC 25
#define G1_CH 400
#define G1_S 4

// ---------------- scratch (device globals; no allocations) ----------------
__device__ __align__(128) float g_Z8[G1_KC][BB * FLATN];
__device__ __align__(128) float g_zsum[BB * FLATN];
__device__ __align__(128) float g_adj[BB * FLATN];
__device__ float g_thr[BB];
__device__ __align__(128) float g_x0[BB * NR * 16];
__device__ __align__(128) float g_xl1[BB * NR * 1024];
__device__ __align__(128) float g_xr1[BB * NR * 1024];
__device__ __align__(128) float g_h1[BB * NR * 1024];
__device__ __align__(128) float g_xl2[BB * NR * 1024];
__device__ __align__(128) float g_xr2[BB * NR * 1024];
__device__ __align__(128) float g_h2[BB * NR * 1024];
__device__ __align__(128) float g_xl3[BB * NR * 128];
__device__ __align__(128) float g_xr3[BB * NR * 128];

__device__ __forceinline__ float sigm(float x) { return 1.f / (1.f + expf(-x)); }
__device__ __forceinline__ float geluf(float x) { return 0.5f * x * (1.f + erff(x * 0.70710678118654752f)); }
__device__ __forceinline__ unsigned f2tf(float x) {
    unsigned u;
    asm("cvt.rna.tf32.f32 %0, %1;" : "=r"(u) : "f"(x));
    return u;
}
__device__ __forceinline__ void mma_tf32(float* d, const unsigned* a, const unsigned* b) {
    asm volatile(
        "mma.sync.aligned.m16n8k8.row.col.f32.tf32.tf32.f32 "
        "{%0,%1,%2,%3},{%4,%5,%6,%7},{%8,%9},{%0,%1,%2,%3};\n"
        : "+f"(d[0]), "+f"(d[1]), "+f"(d[2]), "+f"(d[3])
        : "r"(a[0]), "r"(a[1]), "r"(a[2]), "r"(a[3]), "r"(b[0]), "r"(b[1]));
}
__device__ __forceinline__ void mma_bf16(float* d, const unsigned* a, const unsigned* b) {
    asm volatile(
        "mma.sync.aligned.m16n8k16.row.col.f32.bf16.bf16.f32 "
        "{%0,%1,%2,%3},{%4,%5,%6,%7},{%8,%9},{%0,%1,%2,%3};\n"
        : "+f"(d[0]), "+f"(d[1]), "+f"(d[2]), "+f"(d[3])
        : "r"(a[0]), "r"(a[1]), "r"(a[2]), "r"(a[3]), "r"(b[0]), "r"(b[1]));
}
__device__ __forceinline__ unsigned pack_bf(float x, float y) {
    __nv_bfloat162 t = __floats2bfloat162_rn(x, y);
    return *(unsigned*)&t;
}
__device__ __forceinline__ void hilo2(float x, float y, unsigned& hi, unsigned& lo) {
    float hx = __bfloat162float(__float2bfloat16(x));
    float hy = __bfloat162float(__float2bfloat16(y));
    hi = pack_bf(x, y);
    lo = pack_bf(x - hx, y - hy);
}

// ---------------- GEMM1 v6: 4-stage cp.async pipeline, consumer-side bf16 hi/lo ----------------
__global__ __launch_bounds__(256) void gemm1_v6(const float* __restrict__ A,
                                                const float* __restrict__ W) {
    constexpr int WST = 132;
    constexpr int AST = 20;
    __shared__ __align__(16) float Wb[G1_S][16 * WST];
    __shared__ __align__(16) float Ab[G1_S][16 * AST];
    int tid = threadIdx.x;
    int n0 = blockIdx.x * 128;
    int kc = blockIdx.y;
    int kbeg = kc * G1_CH;
    int w = tid >> 5, lane = tid & 31, gid = lane >> 2, tig = lane & 3;
    int wn0 = w * 16;
    float acc[2][4] = {};

    auto issue = [&](int step, int buf) {
        int k0 = kbeg + step * 16;
#pragma unroll
        for (int l = 0; l < 2; ++l) {
            int c = tid + l * 256;
            int row = c >> 5, col = (c & 31) * 4;
            int gn = n0 + col;
            const float* src = W + (size_t)(k0 + row) * FLATN + ((gn + 4 <= FLATN) ? gn : 0);
            int sz = (gn + 4 <= FLATN) ? 16 : 0;
            unsigned dst = (unsigned)__cvta_generic_to_shared(&Wb[buf][row * WST + col]);
            asm volatile("cp.async.cg.shared.global [%0], [%1], 16, %2;\n"
                         :: "r"(dst), "l"(src), "r"(sz));
        }
        if (tid < 128) {
            int m = tid >> 3, cc = (tid & 7) * 2;
            const float* src = A + (size_t)m * FLATN + k0 + cc;
            unsigned dst = (unsigned)__cvta_generic_to_shared(&Ab[buf][m * AST + cc]);
            asm volatile("cp.async.ca.shared.global [%0], [%1], 8;\n" :: "r"(dst), "l"(src));
        }
        asm volatile("cp.async.commit_group;\n");
    };

    const int NSTEP = G1_CH / 16;  // 25
#pragma unroll
    for (int s = 0; s < G1_S - 1; ++s) issue(s, s);

    for (int s = 0; s < NSTEP; ++s) {
        asm volatile("cp.async.wait_group %0;\n" :: "n"(G1_S - 2));
        __syncthreads();
        int nb = s + G1_S - 1;
        if (nb < NSTEP) issue(nb, nb & 3);
        else asm volatile("cp.async.commit_group;\n");

        const float* Wc = Wb[s & 3];
        const float* Ac = Ab[s & 3];
        unsigned ah[4], al[4];
        {
            float2 p00 = *(const float2*)&Ac[gid * AST + 2 * tig];
            float2 p10 = *(const float2*)&Ac[(gid + 8) * AST + 2 * tig];
            float2 p01 = *(const float2*)&Ac[gid * AST + 2 * tig + 8];
            float2 p11 = *(const float2*)&Ac[(gid + 8) * AST + 2 * tig + 8];
            hilo2(p00.x, p00.y, ah[0], al[0]);
            hilo2(p10.x, p10.y, ah[1], al[1]);
            hilo2(p01.x, p01.y, ah[2], al[2]);
            hilo2(p11.x, p11.y, ah[3], al[3]);
        }
#pragma unroll
        for (int nf = 0; nf < 2; ++nf) {
            int n = wn0 + nf * 8 + gid;
            float w00 = Wc[(2 * tig) * WST + n];
            float w01 = Wc[(2 * tig + 1) * WST + n];
            float w10 = Wc[(2 * tig + 8) * WST + n];
            float w11 = Wc[(2 * tig + 9) * WST + n];
            unsigned bh[2], bl[2];
            hilo2(w00, w01, bh[0], bl[0]);
            hilo2(w10, w11, bh[1], bl[1]);
            mma_bf16(acc[nf], ah, bh);
            mma_bf16(acc[nf], ah, bl);
            mma_bf16(acc[nf], al, bh);
        }
    }
#pragma unroll
    for (int nf = 0; nf < 2; ++nf) {
        int col = n0 + wn0 + nf * 8 + tig * 2;
        if (col < FLATN) {
            float* Z = g_Z8[kc];
            *(float2*)(Z + gid * FLATN + col) = make_float2(acc[nf][0], acc[nf][1]);
            *(float2*)(Z + (gid + 8) * FLATN + col) = make_float2(acc[nf][2], acc[nf][3]);
        }
    }
}

// ---------------- reduce split-K partials + gbb into g_zsum (fully coalesced) ----------------
__global__ __launch_bounds__(256) void reduce_z(const float* __restrict__ gbb) {
    int idx4 = blockIdx.x * 256 + threadIdx.x;  // float4 index
    if (idx4 * 4 >= BB * FLATN) return;
    int e = idx4 * 4;
    int col = e % FLATN;  // gbb index (e = b*FLATN + col, FLATN % 4 == 0)
    float4 s = *(const float4*)(gbb + col);
#pragma unroll
    for (int c = 0; c < G1_KC; ++c) {
        float4 v = *(const float4*)(g_Z8[c] + e);
        s.x += v.x; s.y += v.y; s.z += v.z; s.w += v.w;
    }
    *(float4*)(g_zsum + e) = s;
}

// ---------------- sigmoid/symmetrize + row stats + feature-enhancer MLP + LN ----------------
__global__ __launch_bounds__(128) void stats_fe_kernel(const float* __restrict__ W1,
                                                       const float* __restrict__ b1,
                                                       const float* __restrict__ W2,
                                                       const float* __restrict__ b2,
                                                       const float* __restrict__ gam,
                                                       const float* __restrict__ beta) {
    int i = blockIdx.x, b = blockIdx.y, tid = threadIdx.x;
    __shared__ float sred[128];
    __shared__ float ms[2];
    float a = 0.f;
    if (tid < NR) {
        float zij = g_zsum[b * FLATN + i * NR + tid];
        float zji = g_zsum[b * FLATN + tid * NR + i];
        a = 0.5f * (sigm(zij) + sigm(zji));
        g_adj[b * FLATN + i * NR + tid] = a;
    }
    sred[tid] = a;
    __syncthreads();
    for (int s = 64; s > 0; s >>= 1) {
        if (tid < s) sred[tid] += sred[tid + s];
        __syncthreads();
    }
    if (tid == 0) ms[0] = sred[0] * 0.01f;
    __syncthreads();
    float mean = ms[0];
    float d0 = (tid < NR) ? (a - mean) : 0.f;
    sred[tid] = d0 * d0;
    __syncthreads();
    for (int s = 64; s > 0; s >>= 1) {
        if (tid < s) sred[tid] += sred[tid + s];
        __syncthreads();
    }
    if (tid == 0) ms[1] = sqrtf(fmaxf(sred[0] * (1.f / 99.f), 0.f)) + 1e-6f;
    __syncthreads();

    if (tid < 16) {
        float m = ms[0], s = ms[1];
        float acc = b2[tid];
#pragma unroll
        for (int hh = 0; hh < 8; ++hh) {
            float t = m * W1[hh] + s * W1[8 + hh] + b1[hh];
            acc += geluf(t) * W2[hh * 16 + tid];
        }
        float mu = acc;
#pragma unroll
        for (int off = 8; off > 0; off >>= 1) mu += __shfl_xor_sync(0xffffu, mu, off);
        mu *= (1.f / 16.f);
        float d = acc - mu;
        float vv = d * d;
#pragma unroll
        for (int off = 8; off > 0; off >>= 1) vv += __shfl_xor_sync(0xffffu, vv, off);
        vv *= (1.f / 16.f);
        g_x0[(b * NR + i) * 16 + tid] = d / sqrtf(vv + 1e-5f) * gam[tid] + beta[tid];
    }
}

// ---------------- per-batch 0.75 quantile + zero d_out for pooled atomics ----------------
__global__ __launch_bounds__(512) void quantile_kernel(float* __restrict__ outp) {
    __shared__ __align__(16) unsigned vals[FLATN];
    __shared__ unsigned hist[256];
    __shared__ unsigned s_prefix, s_rank;
    __shared__ unsigned redc[64], redm[64];
    int b = blockIdx.x, tid = threadIdx.x, lane = tid & 31, w = tid >> 5;
    if (tid < 128) outp[b * 128 + tid] = 0.f;
    const float* row = g_adj + b * FLATN;
    for (int i = tid; i < FLATN; i += 512) vals[i] = __float_as_uint(row[i]);
    __syncthreads();

    unsigned rank = 7499;
    unsigned prefix = 0, pmask = 0;
#pragma unroll
    for (int byte = 3; byte >= 0; --byte) {
        int shift = byte * 8;
        if (tid < 256) hist[tid] = 0;
        __syncthreads();
        for (int base = 0; base < FLATN; base += 512) {
            int i = base + tid;
            bool valid = i < FLATN;
            unsigned v = valid ? vals[i] : 0u;
            bool take = valid && ((v & pmask) == prefix);
            unsigned bin = (v >> shift) & 255u;
            unsigned key = take ? bin : 0xFFFFFFFFu;
            unsigned peers = __match_any_sync(0xFFFFFFFFu, key);
            if (take && ((unsigned)(__ffs(peers) - 1) == (unsigned)lane))
                atomicAdd(&hist[bin], __popc(peers));
        }
        __syncthreads();
        if (tid < 32) {
            unsigned base8 = tid * 8;
            unsigned loc = 0;
#pragma unroll
            for (int t = 0; t < 8; ++t) loc += hist[base8 + t];
            unsigned inc = loc;
#pragma unroll
            for (int off = 1; off < 32; off <<= 1) {
                unsigned v = __shfl_up_sync(0xFFFFFFFFu, inc, off);
                if (lane >= off) inc += v;
            }
            unsigned exc = inc - loc;
            if (rank >= exc && rank < exc + loc) {
                unsigned cum = exc, t = base8;
                while (cum + hist[t] <= rank) { cum += hist[t]; ++t; }
                s_prefix = prefix | (t << shift);
                s_rank = rank - cum;
            }
        }
        __syncthreads();
        prefix = s_prefix;
        rank = s_rank;
        pmask |= 0xFFu << shift;
        __syncthreads();
    }
    unsigned v0b = prefix;

    unsigned cle = 0, mab = 0xFFFFFFFFu;
    for (int i = tid; i < FLATN; i += 512) {
        unsigned v = vals[i];
        if (v <= v0b) ++cle;
        else mab = min(mab, v);
    }
#pragma unroll
    for (int off = 16; off > 0; off >>= 1) {
        cle += __shfl_xor_sync(0xFFFFFFFFu, cle, off);
        mab = min(mab, __shfl_xor_sync(0xFFFFFFFFu, mab, off));
    }
    if (lane == 0) { redc[w] = cle; redm[w] = mab; }
    __syncthreads();
    if (tid == 0) {
        unsigned tc = 0, tm = 0xFFFFFFFFu;
        for (int t = 0; t < 16; ++t) { tc += redc[t]; tm = min(tm, redm[t]); }
        unsigned v1b = (tc >= 7501u) ? v0b : tm;
        float v0 = __uint_as_float(v0b), v1 = __uint_as_float(v1b);
        g_thr[b] = v0 + 0.25f * (v1 - v0);
    }
}

// ---------------- fp32 tiled GEMM, fused L/R via blockIdx.z (K=16 layer-1 linears) ----------------
__global__ __launch_bounds__(256) void gemm_tiled2(const float* __restrict__ A,
                                                   const float* __restrict__ W0,
                                                   const float* __restrict__ bi0,
                                                   const float* __restrict__ W1,
                                                   const float* __restrict__ bi1,
                                                   float* __restrict__ C0,
                                                   float* __restrict__ C1,
                                                   int M, int N, int K) {
    __shared__ __align__(16) float As[16][68];
    __shared__ __align__(16) float Bs[16][68];
    const float* W = blockIdx.z ? W1 : W0;
    const float* bias = blockIdx.z ? bi1 : bi0;
    float* Cout = blockIdx.z ? C1 : C0;
    int tid = threadIdx.x;
    int m0 = blockIdx.x * 64, n0 = blockIdx.y * 64;
    int ar = tid >> 2, ak = (tid & 3) << 2;
    int wr = tid >> 4, wc = (tid & 15) << 2;
    int tr = (tid >> 4) << 2, tc = (tid & 15) << 2;
    float acc[4][4] = {};

    for (int k0 = 0; k0 < K; k0 += 16) {
        float4 av = *(const float4*)(A + (size_t)(m0 + ar) * K + k0 + ak);
        As[ak + 0][ar] = av.x;
        As[ak + 1][ar] = av.y;
        As[ak + 2][ar] = av.z;
        As[ak + 3][ar] = av.w;
        *(float4*)&Bs[wr][wc] = *(const float4*)(W + (size_t)(k0 + wr) * N + n0 + wc);
        __syncthreads();
#pragma unroll
        for (int kk = 0; kk < 16; ++kk) {
            float4 a = *(const float4*)&As[kk][tr];
            float4 bv = *(const float4*)&Bs[kk][tc];
            acc[0][0] += a.x * bv.x; acc[0][1] += a.x * bv.y; acc[0][2] += a.x * bv.z; acc[0][3] += a.x * bv.w;
            acc[1][0] += a.y * bv.x; acc[1][1] += a.y * bv.y; acc[1][2] += a.y * bv.z; acc[1][3] += a.y * bv.w;
            acc[2][0] += a.z * bv.x; acc[2][1] += a.z * bv.y; acc[2][2] += a.z * bv.z; acc[2][3] += a.z * bv.w;
            acc[3][0] += a.w * bv.x; acc[3][1] += a.w * bv.y; acc[3][2] += a.w * bv.z; acc[3][3] += a.w * bv.w;
        }
        __syncthreads();
    }
    float4 bb = *(const float4*)(bias + n0 + tc);
#pragma unroll
    for (int u = 0; u < 4; ++u) {
        float4 o = make_float4(acc[u][0] + bb.x, acc[u][1] + bb.y, acc[u][2] + bb.z, acc[u][3] + bb.w);
        *(float4*)(Cout + (size_t)(m0 + tr + u) * N + n0 + tc) = o;
    }
}

// ---------------- tf32 tensor-core GEMM: C = A @ W + bias, fused L/R via blockIdx.z ----------------
template <int BM, int BN, int WM, int WN>
__global__ __launch_bounds__(256) void gemm_tf32(const float* __restrict__ A,
                                                 const float* __restrict__ W0,
                                                 const float* __restrict__ bi0,
                                                 const float* __restrict__ W1,
                                                 const float* __restrict__ bi1,
                                                 float* __restrict__ C0,
                                                 float* __restrict__ C1,
                                                 int M, int N, int K) {
    constexpr int WARPS_M = BM / WM;
    constexpr int MT = WM / 16;
    constexpr int NT = WN / 8;
    constexpr int SA = BM + 8;
    constexpr int SB = BN + 8;
    __shared__ __align__(16) unsigned As[16 * SA];
    __shared__ __align__(16) unsigned Bs[16 * SB];

    const float* W = blockIdx.z ? W1 : W0;
    const float* bi = blockIdx.z ? bi1 : bi0;
    float* C = blockIdx.z ? C1 : C0;

    int tid = threadIdx.x;
    int m0 = blockIdx.x * BM, n0 = blockIdx.y * BN;
    int w = tid >> 5, lane = tid & 31;
    int gid = lane >> 2, tig = lane & 3;
    int wm0 = (w % WARPS_M) * WM;
    int wn0 = (w / WARPS_M) * WN;
    float acc[MT][NT][4] = {};

    for (int k0 = 0; k0 < K; k0 += 16) {
        if (BM == 64) {
            int row = tid >> 2, kq = (tid & 3) * 4;
            float4 v = *(const float4*)(A + (size_t)(m0 + row) * K + k0 + kq);
            As[(kq + 0) * SA + row] = f2tf(v.x);
            As[(kq + 1) * SA + row] = f2tf(v.y);
            As[(kq + 2) * SA + row] = f2tf(v.z);
            As[(kq + 3) * SA + row] = f2tf(v.w);
        } else {
            int row = tid >> 3, kq = (tid & 7) * 2;
            float2 v = *(const float2*)(A + (size_t)(m0 + row) * K + k0 + kq);
            As[(kq + 0) * SA + row] = f2tf(v.x);
            As[(kq + 1) * SA + row] = f2tf(v.y);
        }
#pragma unroll
        for (int l = 0; l < (BN * 16) / 1024; ++l) {
            int idx = tid + l * 256;
            int k = idx / (BN / 4), nq = (idx % (BN / 4)) * 4;
            float4 v = *(const float4*)(W + (size_t)(k0 + k) * N + n0 + nq);
            uint4 u = make_uint4(f2tf(v.x), f2tf(v.y), f2tf(v.z), f2tf(v.w));
            *(uint4*)&Bs[k * SB + nq] = u;
        }
        __syncthreads();
#pragma unroll
        for (int ks = 0; ks < 16; ks += 8) {
            unsigned af[MT][4], bf[NT][2];
#pragma unroll
            for (int mt = 0; mt < MT; ++mt) {
                int m = wm0 + mt * 16 + gid;
                af[mt][0] = As[(ks + tig) * SA + m];
                af[mt][1] = As[(ks + tig) * SA + m + 8];
                af[mt][2] = As[(ks + tig + 4) * SA + m];
                af[mt][3] = As[(ks + tig + 4) * SA + m + 8];
            }
#pragma unroll
            for (int nt = 0; nt < NT; ++nt) {
                int n = wn0 + nt * 8 + gid;
                bf[nt][0] = Bs[(ks + tig) * SB + n];
                bf[nt][1] = Bs[(ks + tig + 4) * SB + n];
            }
#pragma unroll
            for (int mt = 0; mt < MT; ++mt)
#pragma unroll
                for (int nt = 0; nt < NT; ++nt) mma_tf32(acc[mt][nt], af[mt], bf[nt]);
        }
        __syncthreads();
    }
#pragma unroll
    for (int mt = 0; mt < MT; ++mt) {
        int r = m0 + wm0 + mt * 16 + gid;
#pragma unroll
        for (int nt = 0; nt < NT; ++nt) {
            int c = n0 + wn0 + nt * 8 + tig * 2;
            float bv0 = bi[c], bv1 = bi[c + 1];
            *(float2*)(C + (size_t)r * N + c) = make_float2(acc[mt][nt][0] + bv0, acc[mt][nt][1] + bv1);
            *(float2*)(C + (size_t)(r + 8) * N + c) = make_float2(acc[mt][nt][2] + bv0, acc[mt][nt][3] + bv1);
        }
    }
}

// ---------------- fused multi-head GATv2 attention with neighbor compaction ----------------
template <int H, int C, bool SELF, bool POOL>
__global__ __launch_bounds__(H * C) void gat_attn_c(const float* __restrict__ xl,
                                                    const float* __restrict__ xr,
                                                    const float* __restrict__ att,
                                                    const float* __restrict__ adjp,
                                                    const float* __restrict__ thrp,
                                                    const float* __restrict__ bias,
                                                    float* __restrict__ out) {
    constexpr int HC = H * C;
    constexpr int NWARP = HC / 32;
    constexpr int WPH = NWARP / H;
    constexpr int NG = C / 128;
    __shared__ __align__(16) float xr_s[HC];
    __shared__ __align__(16) float att_s[HC];
    __shared__ float e_s[H][104];
    __shared__ int nbr[NR];
    __shared__ int s_cnt;
    int i = blockIdx.x, b = blockIdx.y;
    int tid = threadIdx.x, lane = tid & 31, w = tid >> 5;
    int node = b * NR + i;
    xr_s[tid] = xr[(size_t)node * HC + tid];
    att_s[tid] = att[tid];
    float thrb = thrp[b];
    const float* adjrow = adjp + b * FLATN + i * NR;

    if (w == 0) {
        int cnt = 0;
#pragma unroll
        for (int base = 0; base < 128; base += 32) {
            int j = base + lane;
            bool m = (j < NR) && ((adjrow[j] > thrb) || (SELF && j == i));
            unsigned bal = __ballot_sync(0xFFFFFFFFu, m);
            int pos = cnt + __popc(bal & ((1u << lane) - 1u));
            if (m) nbr[pos] = j;
            cnt += __popc(bal);
        }
        if (lane == 0) s_cnt = cnt;
    }
    __syncthreads();
    int cnt = s_cnt;

    {
        int h = w / WPH, jw = w % WPH;
        const float* xrh = xr_s + h * C;
        const float* ath = att_s + h * C;
        for (int s = jw; s < cnt; s += WPH) {
            int j = nbr[s];
            const float* xlj = xl + (size_t)(b * NR + j) * HC + h * C;
            float p = 0.f;
#pragma unroll
            for (int g = 0; g < NG; ++g) {
                int c = g * 128 + lane * 4;
                float4 xv = *(const float4*)(xlj + c);
                float4 rv = *(const float4*)(xrh + c);
                float4 avv = *(const float4*)(ath + c);
                float s0 = xv.x + rv.x; s0 = (s0 > 0.f) ? s0 : 0.2f * s0; p += s0 * avv.x;
                float s1 = xv.y + rv.y; s1 = (s1 > 0.f) ? s1 : 0.2f * s1; p += s1 * avv.y;
                float s2 = xv.z + rv.z; s2 = (s2 > 0.f) ? s2 : 0.2f * s2; p += s2 * avv.z;
                float s3 = xv.w + rv.w; s3 = (s3 > 0.f) ? s3 : 0.2f * s3; p += s3 * avv.w;
            }
#pragma unroll
            for (int off = 16; off > 0; off >>= 1) p += __shfl_xor_sync(0xffffffffu, p, off);
            if (lane == 0) e_s[h][s] = p;
        }
    }
    __syncthreads();

    if (w < H && cnt > 0) {
        float mx = -3.0e38f;
        for (int s = lane; s < cnt; s += 32) mx = fmaxf(mx, e_s[w][s]);
#pragma unroll
        for (int off = 16; off > 0; off >>= 1) mx = fmaxf(mx, __shfl_xor_sync(0xffffffffu, mx, off));
        float se = 0.f;
        for (int s = lane; s < cnt; s += 32) {
            float t = expf(e_s[w][s] - mx);
            e_s[w][s] = t;
            se += t;
        }
#pragma unroll
        for (int off = 16; off > 0; off >>= 1) se += __shfl_xor_sync(0xffffffffu, se, off);
        float inv = 1.f / se;
        for (int s = lane; s < cnt; s += 32) e_s[w][s] *= inv;
    }
    __syncthreads();

    int hh = tid / C;
    float acc = 0.f;
    const float* xlb = xl + (size_t)(b * NR) * HC + tid;
    int s = 0;
    for (; s + 4 <= cnt; s += 4) {
        float a0 = e_s[hh][s + 0], a1 = e_s[hh][s + 1];
        float a2 = e_s[hh][s + 2], a3 = e_s[hh][s + 3];
        int j0 = nbr[s + 0], j1 = nbr[s + 1], j2 = nbr[s + 2], j3 = nbr[s + 3];
        float v0 = xlb[(size_t)j0 * HC];
        float v1 = xlb[(size_t)j1 * HC];
        float v2 = xlb[(size_t)j2 * HC];
        float v3 = xlb[(size_t)j3 * HC];
        acc += a0 * v0;
        acc += a1 * v1;
        acc += a2 * v2;
        acc += a3 * v3;
    }
    for (; s < cnt; ++s) acc += e_s[hh][s] * xlb[(size_t)nbr[s] * HC];
    float o = geluf(acc + bias[tid]);
    if (POOL) {
        atomicAdd(&out[b * HC + tid], o * 0.01f);
    } else {
        out[(size_t)node * HC + tid] = o;
    }
}

// ---------------- host launcher ----------------
extern "C" void kernel_launch(void* const* d_in, const int* in_sizes, int n_in,
                              void* d_out, int out_size) {
    (void)in_sizes; (void)n_in; (void)out_size;
    const float* raw   = (const float*)d_in[0];
    const float* gbW   = (const float*)d_in[1];
    const float* gbb   = (const float*)d_in[2];
    const float* feW1  = (const float*)d_in[3];
    const float* feb1  = (const float*)d_in[4];
    const float* feW2  = (const float*)d_in[5];
    const float* feb2  = (const float*)d_in[6];
    const float* feg   = (const float*)d_in[7];
    const float* febet = (const float*)d_in[8];
    const float* Wl1   = (const float*)d_in[9];
    const float* bl1   = (const float*)d_in[10];
    const float* Wr1   = (const float*)d_in[11];
    const float* br1   = (const float*)d_in[12];
    const float* att1  = (const float*)d_in[13];
    const float* bias1 = (const float*)d_in[14];
    const float* Wl2   = (const float*)d_in[15];
    const float* bl2   = (const float*)d_in[16];
    const float* Wr2   = (const float*)d_in[17];
    const float* br2   = (const float*)d_in[18];
    const float* att2  = (const float*)d_in[19];
    const float* bias2 = (const float*)d_in[20];
    const float* Wl3   = (const float*)d_in[21];
    const float* bl3   = (const float*)d_in[22];
    const float* Wr3   = (const float*)d_in[23];
    const float* br3   = (const float*)d_in[24];
    const float* att3  = (const float*)d_in[25];
    const float* bias3 = (const float*)d_in[26];

    float *adj, *thr, *x0, *xl1, *xr1, *h1, *xl2, *xr2, *h2, *xl3, *xr3;
    cudaGetSymbolAddress((void**)&adj, g_adj);
    cudaGetSymbolAddress((void**)&thr, g_thr);
    cudaGetSymbolAddress((void**)&x0, g_x0);
    cudaGetSymbolAddress((void**)&xl1, g_xl1);
    cudaGetSymbolAddress((void**)&xr1, g_xr1);
    cudaGetSymbolAddress((void**)&h1, g_h1);
    cudaGetSymbolAddress((void**)&xl2, g_xl2);
    cudaGetSymbolAddress((void**)&xr2, g_xr2);
    cudaGetSymbolAddress((void**)&h2, g_h2);
    cudaGetSymbolAddress((void**)&xl3, g_xl3);
    cudaGetSymbolAddress((void**)&xr3, g_xr3);

    // 1) graph-builder GEMM (cp.async 4-stage pipeline, split-K x25)
    gemm1_v6<<<dim3(79, G1_KC), 256>>>(raw, gbW);
    // 1b) coalesced reduction of split-K partials
    reduce_z<<<(BB * FLATN / 4 + 255) / 256, 256>>>(gbb);
    // 2) adjacency + node features
    stats_fe_kernel<<<dim3(NR, BB), 128>>>(feW1, feb1, feW2, feb2, feg, febet);
    // 3) per-batch 0.75 quantile + d_out zeroing
    quantile_kernel<<<BB, 512>>>((float*)d_out);
    // 4) GAT layer 1 (no self-loops), fused fp32 K=16 linears
    gemm_tiled2<<<dim3(25, 16, 2), 256>>>(x0, Wl1, bl1, Wr1, br1, xl1, xr1, 1600, 1024, 16);
    gat_attn_c<8, 128, false, false><<<dim3(NR, BB), 1024>>>(xl1, xr1, att1, adj, thr, bias1, h1);
    // 5) GAT layer 2 (self-loops)
    gemm_tf32<64, 128, 32, 32><<<dim3(25, 8, 2), 256>>>(h1, Wl2, bl2, Wr2, br2, xl2, xr2, 1600, 1024, 1024);
    gat_attn_c<4, 256, true, false><<<dim3(NR, BB), 1024>>>(xl2, xr2, att2, adj, thr, bias2, h2);
    // 6) GAT layer 3 (self-loops, H=1) + fused mean pool into d_out
    gemm_tf32<32, 128, 32, 16><<<dim3(50, 1, 2), 256>>>(h2, Wl3, bl3, Wr3, br3, xl3, xr3, 1600, 128, 1024);
    gat_attn_c<1, 128, true, true><<<dim3(NR, BB), 128>>>(xl3, xr3, att3, adj, thr, bias3, (float*)d_out);
}

// round 13
// speedup vs baseline: 1.4422x; 1.4422x over previous
#include <cuda_runtime.h>
#include <cuda_bf16.h>
#include <math.h>
#include <float.h>

#define NR 100
#define BB 16
#define FLATN 10000
#define G1_KC 25
#define G1_CH 400
#define G1_S 4

// ---------------- scratch (device globals; no allocations) ----------------
__device__ __align__(128) float g_Z8[G1_KC][BB * FLATN];
__device__ __align__(128) float g_adj[BB * FLATN];
__device__ float g_thr[BB];
__device__ __align__(128) float g_x0[BB * NR * 16];
__device__ __align__(128) float g_xl1[BB * NR * 1024];
__device__ __align__(128) float g_xr1[BB * NR * 1024];
__device__ __align__(128) float g_h1[BB * NR * 1024];
__device__ __align__(128) float g_xl2[BB * NR * 1024];
__device__ __align__(128) float g_xr2[BB * NR * 1024];
__device__ __align__(128) float g_h2[BB * NR * 1024];
__device__ __align__(128) float g_xl3[BB * NR * 128];
__device__ __align__(128) float g_xr3[BB * NR * 128];

__device__ __forceinline__ float sigm(float x) { return 1.f / (1.f + expf(-x)); }
__device__ __forceinline__ float geluf(float x) { return 0.5f * x * (1.f + erff(x * 0.70710678118654752f)); }
__device__ __forceinline__ unsigned f2tf(float x) {
    unsigned u;
    asm("cvt.rna.tf32.f32 %0, %1;" : "=r"(u) : "f"(x));
    return u;
}
__device__ __forceinline__ void mma_tf32(float* d, const unsigned* a, const unsigned* b) {
    asm volatile(
        "mma.sync.aligned.m16n8k8.row.col.f32.tf32.tf32.f32 "
        "{%0,%1,%2,%3},{%4,%5,%6,%7},{%8,%9},{%0,%1,%2,%3};\n"
        : "+f"(d[0]), "+f"(d[1]), "+f"(d[2]), "+f"(d[3])
        : "r"(a[0]), "r"(a[1]), "r"(a[2]), "r"(a[3]), "r"(b[0]), "r"(b[1]));
}
__device__ __forceinline__ void mma_bf16(float* d, const unsigned* a, const unsigned* b) {
    asm volatile(
        "mma.sync.aligned.m16n8k16.row.col.f32.bf16.bf16.f32 "
        "{%0,%1,%2,%3},{%4,%5,%6,%7},{%8,%9},{%0,%1,%2,%3};\n"
        : "+f"(d[0]), "+f"(d[1]), "+f"(d[2]), "+f"(d[3])
        : "r"(a[0]), "r"(a[1]), "r"(a[2]), "r"(a[3]), "r"(b[0]), "r"(b[1]));
}
__device__ __forceinline__ unsigned pack_bf(float x, float y) {
    __nv_bfloat162 t = __floats2bfloat162_rn(x, y);
    return *(unsigned*)&t;
}
__device__ __forceinline__ void hilo2(float x, float y, unsigned& hi, unsigned& lo) {
    float hx = __bfloat162float(__float2bfloat16(x));
    float hy = __bfloat162float(__float2bfloat16(y));
    hi = pack_bf(x, y);
    lo = pack_bf(x - hx, y - hy);
}

// ---------------- GEMM1 v6: 4-stage cp.async pipeline, consumer-side bf16 hi/lo ----------------
__global__ __launch_bounds__(256) void gemm1_v6(const float* __restrict__ A,
                                                const float* __restrict__ W) {
    constexpr int WST = 132;
    constexpr int AST = 20;
    __shared__ __align__(16) float Wb[G1_S][16 * WST];
    __shared__ __align__(16) float Ab[G1_S][16 * AST];
    int tid = threadIdx.x;
    int n0 = blockIdx.x * 128;
    int kc = blockIdx.y;
    int kbeg = kc * G1_CH;
    int w = tid >> 5, lane = tid & 31, gid = lane >> 2, tig = lane & 3;
    int wn0 = w * 16;
    float acc[2][4] = {};

    auto issue = [&](int step, int buf) {
        int k0 = kbeg + step * 16;
#pragma unroll
        for (int l = 0; l < 2; ++l) {
            int c = tid + l * 256;
            int row = c >> 5, col = (c & 31) * 4;
            int gn = n0 + col;
            const float* src = W + (size_t)(k0 + row) * FLATN + ((gn + 4 <= FLATN) ? gn : 0);
            int sz = (gn + 4 <= FLATN) ? 16 : 0;
            unsigned dst = (unsigned)__cvta_generic_to_shared(&Wb[buf][row * WST + col]);
            asm volatile("cp.async.cg.shared.global [%0], [%1], 16, %2;\n"
                         :: "r"(dst), "l"(src), "r"(sz));
        }
        if (tid < 128) {
            int m = tid >> 3, cc = (tid & 7) * 2;
            const float* src = A + (size_t)m * FLATN + k0 + cc;
            unsigned dst = (unsigned)__cvta_generic_to_shared(&Ab[buf][m * AST + cc]);
            asm volatile("cp.async.ca.shared.global [%0], [%1], 8;\n" :: "r"(dst), "l"(src));
        }
        asm volatile("cp.async.commit_group;\n");
    };

    const int NSTEP = G1_CH / 16;  // 25
#pragma unroll
    for (int s = 0; s < G1_S - 1; ++s) issue(s, s);

    for (int s = 0; s < NSTEP; ++s) {
        asm volatile("cp.async.wait_group %0;\n" :: "n"(G1_S - 2));
        __syncthreads();
        int nb = s + G1_S - 1;
        if (nb < NSTEP) issue(nb, nb & 3);
        else asm volatile("cp.async.commit_group;\n");

        const float* Wc = Wb[s & 3];
        const float* Ac = Ab[s & 3];
        unsigned ah[4], al[4];
        {
            float2 p00 = *(const float2*)&Ac[gid * AST + 2 * tig];
            float2 p10 = *(const float2*)&Ac[(gid + 8) * AST + 2 * tig];
            float2 p01 = *(const float2*)&Ac[gid * AST + 2 * tig + 8];
            float2 p11 = *(const float2*)&Ac[(gid + 8) * AST + 2 * tig + 8];
            hilo2(p00.x, p00.y, ah[0], al[0]);
            hilo2(p10.x, p10.y, ah[1], al[1]);
            hilo2(p01.x, p01.y, ah[2], al[2]);
            hilo2(p11.x, p11.y, ah[3], al[3]);
        }
#pragma unroll
        for (int nf = 0; nf < 2; ++nf) {
            int n = wn0 + nf * 8 + gid;
            float w00 = Wc[(2 * tig) * WST + n];
            float w01 = Wc[(2 * tig + 1) * WST + n];
            float w10 = Wc[(2 * tig + 8) * WST + n];
            float w11 = Wc[(2 * tig + 9) * WST + n];
            unsigned bh[2], bl[2];
            hilo2(w00, w01, bh[0], bl[0]);
            hilo2(w10, w11, bh[1], bl[1]);
            mma_bf16(acc[nf], ah, bh);
            mma_bf16(acc[nf], ah, bl);
            mma_bf16(acc[nf], al, bh);
        }
    }
#pragma unroll
    for (int nf = 0; nf < 2; ++nf) {
        int col = n0 + wn0 + nf * 8 + tig * 2;
        if (col < FLATN) {
            float* Z = g_Z8[kc];
            *(float2*)(Z + gid * FLATN + col) = make_float2(acc[nf][0], acc[nf][1]);
            *(float2*)(Z + (gid + 8) * FLATN + col) = make_float2(acc[nf][2], acc[nf][3]);
        }
    }
}

// ---------------- sigmoid/symmetrize + row stats + feature-enhancer MLP + LN ----------------
__global__ __launch_bounds__(128) void stats_fe_kernel(const float* __restrict__ gbb,
                                                       const float* __restrict__ W1,
                                                       const float* __restrict__ b1,
                                                       const float* __restrict__ W2,
                                                       const float* __restrict__ b2,
                                                       const float* __restrict__ gam,
                                                       const float* __restrict__ beta) {
    int i = blockIdx.x, b = blockIdx.y, tid = threadIdx.x;
    __shared__ float sred[128];
    __shared__ float ms[2];
    float a = 0.f;
    if (tid < NR) {
        int eij = b * FLATN + i * NR + tid;
        int eji = b * FLATN + tid * NR + i;
        float zij = gbb[i * NR + tid];
        float zji = gbb[tid * NR + i];
#pragma unroll
        for (int c = 0; c < G1_KC; ++c) {
            zij += g_Z8[c][eij];
            zji += g_Z8[c][eji];
        }
        a = 0.5f * (sigm(zij) + sigm(zji));
        g_adj[b * FLATN + i * NR + tid] = a;
    }
    sred[tid] = a;
    __syncthreads();
    for (int s = 64; s > 0; s >>= 1) {
        if (tid < s) sred[tid] += sred[tid + s];
        __syncthreads();
    }
    if (tid == 0) ms[0] = sred[0] * 0.01f;
    __syncthreads();
    float mean = ms[0];
    float d0 = (tid < NR) ? (a - mean) : 0.f;
    sred[tid] = d0 * d0;
    __syncthreads();
    for (int s = 64; s > 0; s >>= 1) {
        if (tid < s) sred[tid] += sred[tid + s];
        __syncthreads();
    }
    if (tid == 0) ms[1] = sqrtf(fmaxf(sred[0] * (1.f / 99.f), 0.f)) + 1e-6f;
    __syncthreads();

    if (tid < 16) {
        float m = ms[0], s = ms[1];
        float acc = b2[tid];
#pragma unroll
        for (int hh = 0; hh < 8; ++hh) {
            float t = m * W1[hh] + s * W1[8 + hh] + b1[hh];
            acc += geluf(t) * W2[hh * 16 + tid];
        }
        float mu = acc;
#pragma unroll
        for (int off = 8; off > 0; off >>= 1) mu += __shfl_xor_sync(0xffffu, mu, off);
        mu *= (1.f / 16.f);
        float d = acc - mu;
        float vv = d * d;
#pragma unroll
        for (int off = 8; off > 0; off >>= 1) vv += __shfl_xor_sync(0xffffu, vv, off);
        vv *= (1.f / 16.f);
        g_x0[(b * NR + i) * 16 + tid] = d / sqrtf(vv + 1e-5f) * gam[tid] + beta[tid];
    }
}

// ---------------- per-batch 0.75 quantile + zero d_out (1024 threads) ----------------
__global__ __launch_bounds__(1024) void quantile_kernel(float* __restrict__ outp) {
    __shared__ __align__(16) unsigned vals[FLATN];
    __shared__ unsigned hist[256];
    __shared__ unsigned s_prefix, s_rank;
    __shared__ unsigned redc[32], redm[32];
    int b = blockIdx.x, tid = threadIdx.x, lane = tid & 31, w = tid >> 5;
    if (tid < 128) outp[b * 128 + tid] = 0.f;
    const float* row = g_adj + b * FLATN;
    for (int i = tid; i < FLATN; i += 1024) vals[i] = __float_as_uint(row[i]);
    __syncthreads();

    unsigned rank = 7499;
    unsigned prefix = 0, pmask = 0;
#pragma unroll
    for (int byte = 3; byte >= 0; --byte) {
        int shift = byte * 8;
        if (tid < 256) hist[tid] = 0;
        __syncthreads();
        for (int base = 0; base < FLATN; base += 1024) {
            int i = base + tid;
            bool valid = i < FLATN;
            unsigned v = valid ? vals[i] : 0u;
            bool take = valid && ((v & pmask) == prefix);
            unsigned bin = (v >> shift) & 255u;
            unsigned key = take ? bin : 0xFFFFFFFFu;
            unsigned peers = __match_any_sync(0xFFFFFFFFu, key);
            if (take && ((unsigned)(__ffs(peers) - 1) == (unsigned)lane))
                atomicAdd(&hist[bin], __popc(peers));
        }
        __syncthreads();
        if (tid < 32) {
            unsigned base8 = tid * 8;
            unsigned loc = 0;
#pragma unroll
            for (int t = 0; t < 8; ++t) loc += hist[base8 + t];
            unsigned inc = loc;
#pragma unroll
            for (int off = 1; off < 32; off <<= 1) {
                unsigned v = __shfl_up_sync(0xFFFFFFFFu, inc, off);
                if (lane >= off) inc += v;
            }
            unsigned exc = inc - loc;
            if (rank >= exc && rank < exc + loc) {
                unsigned cum = exc, t = base8;
                while (cum + hist[t] <= rank) { cum += hist[t]; ++t; }
                s_prefix = prefix | (t << shift);
                s_rank = rank - cum;
            }
        }
        __syncthreads();
        prefix = s_prefix;
        rank = s_rank;
        pmask |= 0xFFu << shift;
        __syncthreads();
    }
    unsigned v0b = prefix;

    unsigned cle = 0, mab = 0xFFFFFFFFu;
    for (int i = tid; i < FLATN; i += 1024) {
        unsigned v = vals[i];
        if (v <= v0b) ++cle;
        else mab = min(mab, v);
    }
#pragma unroll
    for (int off = 16; off > 0; off >>= 1) {
        cle += __shfl_xor_sync(0xFFFFFFFFu, cle, off);
        mab = min(mab, __shfl_xor_sync(0xFFFFFFFFu, mab, off));
    }
    if (lane == 0) { redc[w] = cle; redm[w] = mab; }
    __syncthreads();
    if (tid == 0) {
        unsigned tc = 0, tm = 0xFFFFFFFFu;
        for (int t = 0; t < 32; ++t) { tc += redc[t]; tm = min(tm, redm[t]); }
        unsigned v1b = (tc >= 7501u) ? v0b : tm;
        float v0 = __uint_as_float(v0b), v1 = __uint_as_float(v1b);
        g_thr[b] = v0 + 0.25f * (v1 - v0);
    }
}

// ---------------- fp32 tiled GEMM, fused L/R via blockIdx.z (K=16 layer-1 linears) ----------------
__global__ __launch_bounds__(256) void gemm_tiled2(const float* __restrict__ A,
                                                   const float* __restrict__ W0,
                                                   const float* __restrict__ bi0,
                                                   const float* __restrict__ W1,
                                                   const float* __restrict__ bi1,
                                                   float* __restrict__ C0,
                                                   float* __restrict__ C1,
                                                   int M, int N, int K) {
    __shared__ __align__(16) float As[16][68];
    __shared__ __align__(16) float Bs[16][68];
    const float* W = blockIdx.z ? W1 : W0;
    const float* bias = blockIdx.z ? bi1 : bi0;
    float* Cout = blockIdx.z ? C1 : C0;
    int tid = threadIdx.x;
    int m0 = blockIdx.x * 64, n0 = blockIdx.y * 64;
    int ar = tid >> 2, ak = (tid & 3) << 2;
    int wr = tid >> 4, wc = (tid & 15) << 2;
    int tr = (tid >> 4) << 2, tc = (tid & 15) << 2;
    float acc[4][4] = {};

    for (int k0 = 0; k0 < K; k0 += 16) {
        float4 av = *(const float4*)(A + (size_t)(m0 + ar) * K + k0 + ak);
        As[ak + 0][ar] = av.x;
        As[ak + 1][ar] = av.y;
        As[ak + 2][ar] = av.z;
        As[ak + 3][ar] = av.w;
        *(float4*)&Bs[wr][wc] = *(const float4*)(W + (size_t)(k0 + wr) * N + n0 + wc);
        __syncthreads();
#pragma unroll
        for (int kk = 0; kk < 16; ++kk) {
            float4 a = *(const float4*)&As[kk][tr];
            float4 bv = *(const float4*)&Bs[kk][tc];
            acc[0][0] += a.x * bv.x; acc[0][1] += a.x * bv.y; acc[0][2] += a.x * bv.z; acc[0][3] += a.x * bv.w;
            acc[1][0] += a.y * bv.x; acc[1][1] += a.y * bv.y; acc[1][2] += a.y * bv.z; acc[1][3] += a.y * bv.w;
            acc[2][0] += a.z * bv.x; acc[2][1] += a.z * bv.y; acc[2][2] += a.z * bv.z; acc[2][3] += a.z * bv.w;
            acc[3][0] += a.w * bv.x; acc[3][1] += a.w * bv.y; acc[3][2] += a.w * bv.z; acc[3][3] += a.w * bv.w;
        }
        __syncthreads();
    }
    float4 bb = *(const float4*)(bias + n0 + tc);
#pragma unroll
    for (int u = 0; u < 4; ++u) {
        float4 o = make_float4(acc[u][0] + bb.x, acc[u][1] + bb.y, acc[u][2] + bb.z, acc[u][3] + bb.w);
        *(float4*)(Cout + (size_t)(m0 + tr + u) * N + n0 + tc) = o;
    }
}

// ---------------- tf32 tensor-core GEMM: C = A @ W + bias, fused L/R via blockIdx.z ----------------
template <int BM, int BN, int WM, int WN>
__global__ __launch_bounds__(256) void gemm_tf32(const float* __restrict__ A,
                                                 const float* __restrict__ W0,
                                                 const float* __restrict__ bi0,
                                                 const float* __restrict__ W1,
                                                 const float* __restrict__ bi1,
                                                 float* __restrict__ C0,
                                                 float* __restrict__ C1,
                                                 int M, int N, int K) {
    constexpr int WARPS_M = BM / WM;
    constexpr int MT = WM / 16;
    constexpr int NT = WN / 8;
    constexpr int SA = BM + 8;
    constexpr int SB = BN + 8;
    __shared__ __align__(16) unsigned As[16 * SA];
    __shared__ __align__(16) unsigned Bs[16 * SB];

    const float* W = blockIdx.z ? W1 : W0;
    const float* bi = blockIdx.z ? bi1 : bi0;
    float* C = blockIdx.z ? C1 : C0;

    int tid = threadIdx.x;
    int m0 = blockIdx.x * BM, n0 = blockIdx.y * BN;
    int w = tid >> 5, lane = tid & 31;
    int gid = lane >> 2, tig = lane & 3;
    int wm0 = (w % WARPS_M) * WM;
    int wn0 = (w / WARPS_M) * WN;
    float acc[MT][NT][4] = {};

    for (int k0 = 0; k0 < K; k0 += 16) {
        if (BM == 64) {
            int row = tid >> 2, kq = (tid & 3) * 4;
            float4 v = *(const float4*)(A + (size_t)(m0 + row) * K + k0 + kq);
            As[(kq + 0) * SA + row] = f2tf(v.x);
            As[(kq + 1) * SA + row] = f2tf(v.y);
            As[(kq + 2) * SA + row] = f2tf(v.z);
            As[(kq + 3) * SA + row] = f2tf(v.w);
        } else {
            int row = tid >> 3, kq = (tid & 7) * 2;
            float2 v = *(const float2*)(A + (size_t)(m0 + row) * K + k0 + kq);
            As[(kq + 0) * SA + row] = f2tf(v.x);
            As[(kq + 1) * SA + row] = f2tf(v.y);
        }
#pragma unroll
        for (int l = 0; l < (BN * 16) / 1024; ++l) {
            int idx = tid + l * 256;
            int k = idx / (BN / 4), nq = (idx % (BN / 4)) * 4;
            float4 v = *(const float4*)(W + (size_t)(k0 + k) * N + n0 + nq);
            uint4 u = make_uint4(f2tf(v.x), f2tf(v.y), f2tf(v.z), f2tf(v.w));
            *(uint4*)&Bs[k * SB + nq] = u;
        }
        __syncthreads();
#pragma unroll
        for (int ks = 0; ks < 16; ks += 8) {
            unsigned af[MT][4], bf[NT][2];
#pragma unroll
            for (int mt = 0; mt < MT; ++mt) {
                int m = wm0 + mt * 16 + gid;
                af[mt][0] = As[(ks + tig) * SA + m];
                af[mt][1] = As[(ks + tig) * SA + m + 8];
                af[mt][2] = As[(ks + tig + 4) * SA + m];
                af[mt][3] = As[(ks + tig + 4) * SA + m + 8];
            }
#pragma unroll
            for (int nt = 0; nt < NT; ++nt) {
                int n = wn0 + nt * 8 + gid;
                bf[nt][0] = Bs[(ks + tig) * SB + n];
                bf[nt][1] = Bs[(ks + tig + 4) * SB + n];
            }
#pragma unroll
            for (int mt = 0; mt < MT; ++mt)
#pragma unroll
                for (int nt = 0; nt < NT; ++nt) mma_tf32(acc[mt][nt], af[mt], bf[nt]);
        }
        __syncthreads();
    }
#pragma unroll
    for (int mt = 0; mt < MT; ++mt) {
        int r = m0 + wm0 + mt * 16 + gid;
#pragma unroll
        for (int nt = 0; nt < NT; ++nt) {
            int c = n0 + wn0 + nt * 8 + tig * 2;
            float bv0 = bi[c], bv1 = bi[c + 1];
            *(float2*)(C + (size_t)r * N + c) = make_float2(acc[mt][nt][0] + bv0, acc[mt][nt][1] + bv1);
            *(float2*)(C + (size_t)(r + 8) * N + c) = make_float2(acc[mt][nt][2] + bv0, acc[mt][nt][3] + bv1);
        }
    }
}

// ---------------- fused multi-head GATv2 attention with neighbor compaction ----------------
template <int H, int C, bool SELF, bool POOL>
__global__ __launch_bounds__(H * C) void gat_attn_c(const float* __restrict__ xl,
                                                    const float* __restrict__ xr,
                                                    const float* __restrict__ att,
                                                    const float* __restrict__ adjp,
                                                    const float* __restrict__ thrp,
                                                    const float* __restrict__ bias,
                                                    float* __restrict__ out) {
    constexpr int HC = H * C;
    constexpr int NWARP = HC / 32;
    constexpr int WPH = NWARP / H;
    constexpr int NG = C / 128;
    __shared__ __align__(16) float xr_s[HC];
    __shared__ __align__(16) float att_s[HC];
    __shared__ float e_s[H][104];
    __shared__ int nbr[NR];
    __shared__ int s_cnt;
    int i = blockIdx.x, b = blockIdx.y;
    int tid = threadIdx.x, lane = tid & 31, w = tid >> 5;
    int node = b * NR + i;
    xr_s[tid] = xr[(size_t)node * HC + tid];
    att_s[tid] = att[tid];
    float thrb = thrp[b];
    const float* adjrow = adjp + b * FLATN + i * NR;

    if (w == 0) {
        int cnt = 0;
#pragma unroll
        for (int base = 0; base < 128; base += 32) {
            int j = base + lane;
            bool m = (j < NR) && ((adjrow[j] > thrb) || (SELF && j == i));
            unsigned bal = __ballot_sync(0xFFFFFFFFu, m);
            int pos = cnt + __popc(bal & ((1u << lane) - 1u));
            if (m) nbr[pos] = j;
            cnt += __popc(bal);
        }
        if (lane == 0) s_cnt = cnt;
    }
    __syncthreads();
    int cnt = s_cnt;

    {
        int h = w / WPH, jw = w % WPH;
        const float* xrh = xr_s + h * C;
        const float* ath = att_s + h * C;
        for (int s = jw; s < cnt; s += WPH) {
            int j = nbr[s];
            const float* xlj = xl + (size_t)(b * NR + j) * HC + h * C;
            float p = 0.f;
#pragma unroll
            for (int g = 0; g < NG; ++g) {
                int c = g * 128 + lane * 4;
                float4 xv = *(const float4*)(xlj + c);
                float4 rv = *(const float4*)(xrh + c);
                float4 avv = *(const float4*)(ath + c);
                float s0 = xv.x + rv.x; s0 = (s0 > 0.f) ? s0 : 0.2f * s0; p += s0 * avv.x;
                float s1 = xv.y + rv.y; s1 = (s1 > 0.f) ? s1 : 0.2f * s1; p += s1 * avv.y;
                float s2 = xv.z + rv.z; s2 = (s2 > 0.f) ? s2 : 0.2f * s2; p += s2 * avv.z;
                float s3 = xv.w + rv.w; s3 = (s3 > 0.f) ? s3 : 0.2f * s3; p += s3 * avv.w;
            }
#pragma unroll
            for (int off = 16; off > 0; off >>= 1) p += __shfl_xor_sync(0xffffffffu, p, off);
            if (lane == 0) e_s[h][s] = p;
        }
    }
    __syncthreads();

    if (w < H && cnt > 0) {
        float mx = -3.0e38f;
        for (int s = lane; s < cnt; s += 32) mx = fmaxf(mx, e_s[w][s]);
#pragma unroll
        for (int off = 16; off > 0; off >>= 1) mx = fmaxf(mx, __shfl_xor_sync(0xffffffffu, mx, off));
        float se = 0.f;
        for (int s = lane; s < cnt; s += 32) {
            float t = expf(e_s[w][s] - mx);
            e_s[w][s] = t;
            se += t;
        }
#pragma unroll
        for (int off = 16; off > 0; off >>= 1) se += __shfl_xor_sync(0xffffffffu, se, off);
        float inv = 1.f / se;
        for (int s = lane; s < cnt; s += 32) e_s[w][s] *= inv;
    }
    __syncthreads();

    int hh = tid / C;
    float acc = 0.f;
    const float* xlb = xl + (size_t)(b * NR) * HC + tid;
    int s = 0;
    for (; s + 4 <= cnt; s += 4) {
        float a0 = e_s[hh][s + 0], a1 = e_s[hh][s + 1];
        float a2 = e_s[hh][s + 2], a3 = e_s[hh][s + 3];
        int j0 = nbr[s + 0], j1 = nbr[s + 1], j2 = nbr[s + 2], j3 = nbr[s + 3];
        float v0 = xlb[(size_t)j0 * HC];
        float v1 = xlb[(size_t)j1 * HC];
        float v2 = xlb[(size_t)j2 * HC];
        float v3 = xlb[(size_t)j3 * HC];
        acc += a0 * v0;
        acc += a1 * v1;
        acc += a2 * v2;
        acc += a3 * v3;
    }
    for (; s < cnt; ++s) acc += e_s[hh][s] * xlb[(size_t)nbr[s] * HC];
    float o = geluf(acc + bias[tid]);
    if (POOL) {
        atomicAdd(&out[b * HC + tid], o * 0.01f);
    } else {
        out[(size_t)node * HC + tid] = o;
    }
}

// ---------------- host launcher ----------------
extern "C" void kernel_launch(void* const* d_in, const int* in_sizes, int n_in,
                              void* d_out, int out_size) {
    (void)in_sizes; (void)n_in; (void)out_size;
    const float* raw   = (const float*)d_in[0];
    const float* gbW   = (const float*)d_in[1];
    const float* gbb   = (const float*)d_in[2];
    const float* feW1  = (const float*)d_in[3];
    const float* feb1  = (const float*)d_in[4];
    const float* feW2  = (const float*)d_in[5];
    const float* feb2  = (const float*)d_in[6];
    const float* feg   = (const float*)d_in[7];
    const float* febet = (const float*)d_in[8];
    const float* Wl1   = (const float*)d_in[9];
    const float* bl1   = (const float*)d_in[10];
    const float* Wr1   = (const float*)d_in[11];
    const float* br1   = (const float*)d_in[12];
    const float* att1  = (const float*)d_in[13];
    const float* bias1 = (const float*)d_in[14];
    const float* Wl2   = (const float*)d_in[15];
    const float* bl2   = (const float*)d_in[16];
    const float* Wr2   = (const float*)d_in[17];
    const float* br2   = (const float*)d_in[18];
    const float* att2  = (const float*)d_in[19];
    const float* bias2 = (const float*)d_in[20];
    const float* Wl3   = (const float*)d_in[21];
    const float* bl3   = (const float*)d_in[22];
    const float* Wr3   = (const float*)d_in[23];
    const float* br3   = (const float*)d_in[24];
    const float* att3  = (const float*)d_in[25];
    const float* bias3 = (const float*)d_in[26];

    float *adj, *thr, *x0, *xl1, *xr1, *h1, *xl2, *xr2, *h2, *xl3, *xr3;
    cudaGetSymbolAddress((void**)&adj, g_adj);
    cudaGetSymbolAddress((void**)&thr, g_thr);
    cudaGetSymbolAddress((void**)&x0, g_x0);
    cudaGetSymbolAddress((void**)&xl1, g_xl1);
    cudaGetSymbolAddress((void**)&xr1, g_xr1);
    cudaGetSymbolAddress((void**)&h1, g_h1);
    cudaGetSymbolAddress((void**)&xl2, g_xl2);
    cudaGetSymbolAddress((void**)&xr2, g_xr2);
    cudaGetSymbolAddress((void**)&h2, g_h2);
    cudaGetSymbolAddress((void**)&xl3, g_xl3);
    cudaGetSymbolAddress((void**)&xr3, g_xr3);

    // 1) graph-builder GEMM (cp.async 4-stage pipeline, split-K x25)
    gemm1_v6<<<dim3(79, G1_KC), 256>>>(raw, gbW);
    // 2) adjacency + node features
    stats_fe_kernel<<<dim3(NR, BB), 128>>>(gbb, feW1, feb1, feW2, feb2, feg, febet);
    // 3) per-batch 0.75 quantile + d_out zeroing (1024 threads)
    quantile_kernel<<<BB, 1024>>>((float*)d_out);
    // 4) GAT layer 1 (no self-loops), fused fp32 K=16 linears
    gemm_tiled2<<<dim3(25, 16, 2), 256>>>(x0, Wl1, bl1, Wr1, br1, xl1, xr1, 1600, 1024, 16);
    gat_attn_c<8, 128, false, false><<<dim3(NR, BB), 1024>>>(xl1, xr1, att1, adj, thr, bias1, h1);
    // 5) GAT layer 2 (self-loops)
    gemm_tf32<64, 128, 32, 32><<<dim3(25, 8, 2), 256>>>(h1, Wl2, bl2, Wr2, br2, xl2, xr2, 1600, 1024, 1024);
    gat_attn_c<4, 256, true, false><<<dim3(NR, BB), 1024>>>(xl2, xr2, att2, adj, thr, bias2, h2);
    // 6) GAT layer 3 (self-loops, H=1) + fused mean pool into d_out
    gemm_tf32<32, 128, 32, 16><<<dim3(50, 1, 2), 256>>>(h2, Wl3, bl3, Wr3, br3, xl3, xr3, 1600, 128, 1024);
    gat_attn_c<1, 128, true, true><<<dim3(NR, BB), 128>>>(xl3, xr3, att3, adj, thr, bias3, (float*)d_out);
}

// round 15
// speedup vs baseline: 1.4555x; 1.0092x over previous
#include <cuda_runtime.h>
#include <cuda_bf16.h>
#include <math.h>
#include <float.h>

#define NR 100
#define BB 16
#define FLATN 10000
#define G1_KC 25
#define G1_CH 400
#define G1_S 4

// ---------------- scratch (device globals; no allocations) ----------------
__device__ __align__(128) float g_Z8[G1_KC][BB * FLATN];
__device__ __align__(128) float g_adj[BB * FLATN];
__device__ float g_thr[BB];
__device__ __align__(128) float g_x0[BB * NR * 16];
__device__ __align__(128) float g_xl1[BB * NR * 1024];
__device__ __align__(128) float g_xr1[BB * NR * 1024];
__device__ __align__(128) float g_h1[BB * NR * 1024];
__device__ __align__(128) float g_xl2[BB * NR * 1024];
__device__ __align__(128) float g_xr2[BB * NR * 1024];
__device__ __align__(128) float g_h2[BB * NR * 1024];
__device__ __align__(128) float g_xl3[BB * NR * 128];
__device__ __align__(128) float g_xr3[BB * NR * 128];

__device__ __forceinline__ float sigm(float x) { return 1.f / (1.f + expf(-x)); }
__device__ __forceinline__ float geluf(float x) { return 0.5f * x * (1.f + erff(x * 0.70710678118654752f)); }
__device__ __forceinline__ unsigned f2tf(float x) {
    unsigned u;
    asm("cvt.rna.tf32.f32 %0, %1;" : "=r"(u) : "f"(x));
    return u;
}
__device__ __forceinline__ void mma_tf32(float* d, const unsigned* a, const unsigned* b) {
    asm volatile(
        "mma.sync.aligned.m16n8k8.row.col.f32.tf32.tf32.f32 "
        "{%0,%1,%2,%3},{%4,%5,%6,%7},{%8,%9},{%0,%1,%2,%3};\n"
        : "+f"(d[0]), "+f"(d[1]), "+f"(d[2]), "+f"(d[3])
        : "r"(a[0]), "r"(a[1]), "r"(a[2]), "r"(a[3]), "r"(b[0]), "r"(b[1]));
}
__device__ __forceinline__ void mma_bf16(float* d, const unsigned* a, const unsigned* b) {
    asm volatile(
        "mma.sync.aligned.m16n8k16.row.col.f32.bf16.bf16.f32 "
        "{%0,%1,%2,%3},{%4,%5,%6,%7},{%8,%9},{%0,%1,%2,%3};\n"
        : "+f"(d[0]), "+f"(d[1]), "+f"(d[2]), "+f"(d[3])
        : "r"(a[0]), "r"(a[1]), "r"(a[2]), "r"(a[3]), "r"(b[0]), "r"(b[1]));
}
__device__ __forceinline__ unsigned pack_bf(float x, float y) {
    __nv_bfloat162 t = __floats2bfloat162_rn(x, y);
    return *(unsigned*)&t;
}
__device__ __forceinline__ void hilo2(float x, float y, unsigned& hi, unsigned& lo) {
    float hx = __bfloat162float(__float2bfloat16(x));
    float hy = __bfloat162float(__float2bfloat16(y));
    hi = pack_bf(x, y);
    lo = pack_bf(x - hx, y - hy);
}

// ---------------- GEMM1 v6: 4-stage cp.async pipeline, consumer-side bf16 hi/lo ----------------
__global__ __launch_bounds__(256) void gemm1_v6(const float* __restrict__ A,
                                                const float* __restrict__ W) {
    constexpr int WST = 132;
    constexpr int AST = 20;
    __shared__ __align__(16) float Wb[G1_S][16 * WST];
    __shared__ __align__(16) float Ab[G1_S][16 * AST];
    int tid = threadIdx.x;
    int n0 = blockIdx.x * 128;
    int kc = blockIdx.y;
    int kbeg = kc * G1_CH;
    int w = tid >> 5, lane = tid & 31, gid = lane >> 2, tig = lane & 3;
    int wn0 = w * 16;
    float acc[2][4] = {};

    auto issue = [&](int step, int buf) {
        int k0 = kbeg + step * 16;
#pragma unroll
        for (int l = 0; l < 2; ++l) {
            int c = tid + l * 256;
            int row = c >> 5, col = (c & 31) * 4;
            int gn = n0 + col;
            const float* src = W + (size_t)(k0 + row) * FLATN + ((gn + 4 <= FLATN) ? gn : 0);
            int sz = (gn + 4 <= FLATN) ? 16 : 0;
            unsigned dst = (unsigned)__cvta_generic_to_shared(&Wb[buf][row * WST + col]);
            asm volatile("cp.async.cg.shared.global [%0], [%1], 16, %2;\n"
                         :: "r"(dst), "l"(src), "r"(sz));
        }
        if (tid < 128) {
            int m = tid >> 3, cc = (tid & 7) * 2;
            const float* src = A + (size_t)m * FLATN + k0 + cc;
            unsigned dst = (unsigned)__cvta_generic_to_shared(&Ab[buf][m * AST + cc]);
            asm volatile("cp.async.ca.shared.global [%0], [%1], 8;\n" :: "r"(dst), "l"(src));
        }
        asm volatile("cp.async.commit_group;\n");
    };

    const int NSTEP = G1_CH / 16;  // 25
#pragma unroll
    for (int s = 0; s < G1_S - 1; ++s) issue(s, s);

    for (int s = 0; s < NSTEP; ++s) {
        asm volatile("cp.async.wait_group %0;\n" :: "n"(G1_S - 2));
        __syncthreads();
        int nb = s + G1_S - 1;
        if (nb < NSTEP) issue(nb, nb & 3);
        else asm volatile("cp.async.commit_group;\n");

        const float* Wc = Wb[s & 3];
        const float* Ac = Ab[s & 3];
        unsigned ah[4], al[4];
        {
            float2 p00 = *(const float2*)&Ac[gid * AST + 2 * tig];
            float2 p10 = *(const float2*)&Ac[(gid + 8) * AST + 2 * tig];
            float2 p01 = *(const float2*)&Ac[gid * AST + 2 * tig + 8];
            float2 p11 = *(const float2*)&Ac[(gid + 8) * AST + 2 * tig + 8];
            hilo2(p00.x, p00.y, ah[0], al[0]);
            hilo2(p10.x, p10.y, ah[1], al[1]);
            hilo2(p01.x, p01.y, ah[2], al[2]);
            hilo2(p11.x, p11.y, ah[3], al[3]);
        }
#pragma unroll
        for (int nf = 0; nf < 2; ++nf) {
            int n = wn0 + nf * 8 + gid;
            float w00 = Wc[(2 * tig) * WST + n];
            float w01 = Wc[(2 * tig + 1) * WST + n];
            float w10 = Wc[(2 * tig + 8) * WST + n];
            float w11 = Wc[(2 * tig + 9) * WST + n];
            unsigned bh[2], bl[2];
            hilo2(w00, w01, bh[0], bl[0]);
            hilo2(w10, w11, bh[1], bl[1]);
            mma_bf16(acc[nf], ah, bh);
            mma_bf16(acc[nf], ah, bl);
            mma_bf16(acc[nf], al, bh);
        }
    }
#pragma unroll
    for (int nf = 0; nf < 2; ++nf) {
        int col = n0 + wn0 + nf * 8 + tig * 2;
        if (col < FLATN) {
            float* Z = g_Z8[kc];
            *(float2*)(Z + gid * FLATN + col) = make_float2(acc[nf][0], acc[nf][1]);
            *(float2*)(Z + (gid + 8) * FLATN + col) = make_float2(acc[nf][2], acc[nf][3]);
        }
    }
}

// ---------------- FUSED: zsum + adjacency + row stats + FE MLP/LN + quantile ----------------
// One block per batch, 1024 threads, 80 KB dynamic smem (zs[10000], adjs[10000]).
__global__ __launch_bounds__(1024) void fused_stats_quant(const float* __restrict__ gbb,
                                                          const float* __restrict__ W1,
                                                          const float* __restrict__ b1,
                                                          const float* __restrict__ W2,
                                                          const float* __restrict__ b2,
                                                          const float* __restrict__ gam,
                                                          const float* __restrict__ beta,
                                                          float* __restrict__ outp) {
    extern __shared__ float smem[];
    float* zs = smem;             // FLATN floats
    float* adjs = smem + FLATN;   // FLATN floats
    __shared__ unsigned hist[256];
    __shared__ float m_s[NR], s_s[NR];
    __shared__ unsigned s_prefix, s_rank;
    __shared__ unsigned redc[32], redm[32];
    int b = blockIdx.x, tid = threadIdx.x, lane = tid & 31, w = tid >> 5;
    if (tid < 128) outp[b * 128 + tid] = 0.f;

    // phase 1: coalesced reduction of split-K partials (+ gbb) into smem
    for (int idx = tid; idx < FLATN; idx += 1024) {
        float s = gbb[idx];
#pragma unroll
        for (int c = 0; c < G1_KC; ++c) s += g_Z8[c][b * FLATN + idx];
        zs[idx] = s;
    }
    __syncthreads();

    // phase 2: sigmoid + symmetrize (transposed read is LDS), write g_adj coalesced
    for (int idx = tid; idx < FLATN; idx += 1024) {
        int i = idx / NR, j = idx - i * NR;
        float a = 0.5f * (sigm(zs[idx]) + sigm(zs[j * NR + i]));
        adjs[idx] = a;
        g_adj[b * FLATN + idx] = a;
    }
    __syncthreads();

    // phase 3: per-row mean / unbiased std (one warp per row, rows strided by 32)
    for (int r = w; r < NR; r += 32) {
        const float* row = adjs + r * NR;
        float v0 = row[lane];
        float v1 = row[lane + 32];
        float v2 = row[lane + 64];
        float v3 = (lane < 4) ? row[lane + 96] : 0.f;
        float su = v0 + v1 + v2 + v3;
#pragma unroll
        for (int off = 16; off > 0; off >>= 1) su += __shfl_xor_sync(0xFFFFFFFFu, su, off);
        float mean = su * 0.01f;
        float d0 = v0 - mean, d1 = v1 - mean, d2 = v2 - mean;
        float d3 = (lane < 4) ? (v3 - mean) : 0.f;
        float sq = d0 * d0 + d1 * d1 + d2 * d2 + d3 * d3;
#pragma unroll
        for (int off = 16; off > 0; off >>= 1) sq += __shfl_xor_sync(0xFFFFFFFFu, sq, off);
        if (lane == 0) {
            m_s[r] = mean;
            s_s[r] = sqrtf(fmaxf(sq * (1.f / 99.f), 0.f)) + 1e-6f;
        }
    }
    __syncthreads();

    // phase 4: feature-enhancer MLP + LayerNorm(16); strided over all 1600 elems
    // (1600 = 1024 + 576; 576 % 32 == 0 -> second pass is warp-uniform)
    for (int t = tid; t < NR * 16; t += 1024) {
        int r = t >> 4, ch = t & 15;
        float m = m_s[r], s = s_s[r];
        float acc = b2[ch];
#pragma unroll
        for (int hh = 0; hh < 8; ++hh) {
            float tt = m * W1[hh] + s * W1[8 + hh] + b1[hh];
            acc += geluf(tt) * W2[hh * 16 + ch];
        }
        float mu = acc;
#pragma unroll
        for (int off = 8; off > 0; off >>= 1) mu += __shfl_xor_sync(0xFFFFFFFFu, mu, off, 16);
        mu *= (1.f / 16.f);
        float d = acc - mu;
        float vv = d * d;
#pragma unroll
        for (int off = 8; off > 0; off >>= 1) vv += __shfl_xor_sync(0xFFFFFFFFu, vv, off, 16);
        vv *= (1.f / 16.f);
        g_x0[(b * NR + r) * 16 + ch] = d / sqrtf(vv + 1e-5f) * gam[ch] + beta[ch];
    }
    __syncthreads();

    // phase 5: 0.75-quantile radix select over smem adjs
    unsigned rank = 7499;
    unsigned prefix = 0, pmask = 0;
#pragma unroll
    for (int byte = 3; byte >= 0; --byte) {
        int shift = byte * 8;
        if (tid < 256) hist[tid] = 0;
        __syncthreads();
        for (int base = 0; base < FLATN; base += 1024) {
            int i = base + tid;
            bool valid = i < FLATN;
            unsigned v = valid ? __float_as_uint(adjs[i]) : 0u;
            bool take = valid && ((v & pmask) == prefix);
            unsigned bin = (v >> shift) & 255u;
            unsigned key = take ? bin : 0xFFFFFFFFu;
            unsigned peers = __match_any_sync(0xFFFFFFFFu, key);
            if (take && ((unsigned)(__ffs(peers) - 1) == (unsigned)lane))
                atomicAdd(&hist[bin], __popc(peers));
        }
        __syncthreads();
        if (tid < 32) {
            unsigned base8 = tid * 8;
            unsigned loc = 0;
#pragma unroll
            for (int t = 0; t < 8; ++t) loc += hist[base8 + t];
            unsigned inc = loc;
#pragma unroll
            for (int off = 1; off < 32; off <<= 1) {
                unsigned v = __shfl_up_sync(0xFFFFFFFFu, inc, off);
                if (lane >= off) inc += v;
            }
            unsigned exc = inc - loc;
            if (rank >= exc && rank < exc + loc) {
                unsigned cum = exc, t = base8;
                while (cum + hist[t] <= rank) { cum += hist[t]; ++t; }
                s_prefix = prefix | (t << shift);
                s_rank = rank - cum;
            }
        }
        __syncthreads();
        prefix = s_prefix;
        rank = s_rank;
        pmask |= 0xFFu << shift;
        __syncthreads();
    }
    unsigned v0b = prefix;

    unsigned cle = 0, mab = 0xFFFFFFFFu;
    for (int i = tid; i < FLATN; i += 1024) {
        unsigned v = __float_as_uint(adjs[i]);
        if (v <= v0b) ++cle;
        else mab = min(mab, v);
    }
#pragma unroll
    for (int off = 16; off > 0; off >>= 1) {
        cle += __shfl_xor_sync(0xFFFFFFFFu, cle, off);
        mab = min(mab, __shfl_xor_sync(0xFFFFFFFFu, mab, off));
    }
    if (lane == 0) { redc[w] = cle; redm[w] = mab; }
    __syncthreads();
    if (tid == 0) {
        unsigned tc = 0, tm = 0xFFFFFFFFu;
        for (int t = 0; t < 32; ++t) { tc += redc[t]; tm = min(tm, redm[t]); }
        unsigned v1b = (tc >= 7501u) ? v0b : tm;
        float v0 = __uint_as_float(v0b), v1 = __uint_as_float(v1b);
        g_thr[b] = v0 + 0.25f * (v1 - v0);
    }
}

// ---------------- fp32 tiled GEMM, fused L/R via blockIdx.z (K=16 layer-1 linears) ----------------
__global__ __launch_bounds__(256) void gemm_tiled2(const float* __restrict__ A,
                                                   const float* __restrict__ W0,
                                                   const float* __restrict__ bi0,
                                                   const float* __restrict__ W1,
                                                   const float* __restrict__ bi1,
                                                   float* __restrict__ C0,
                                                   float* __restrict__ C1,
                                                   int M, int N, int K) {
    __shared__ __align__(16) float As[16][68];
    __shared__ __align__(16) float Bs[16][68];
    const float* W = blockIdx.z ? W1 : W0;
    const float* bias = blockIdx.z ? bi1 : bi0;
    float* Cout = blockIdx.z ? C1 : C0;
    int tid = threadIdx.x;
    int m0 = blockIdx.x * 64, n0 = blockIdx.y * 64;
    int ar = tid >> 2, ak = (tid & 3) << 2;
    int wr = tid >> 4, wc = (tid & 15) << 2;
    int tr = (tid >> 4) << 2, tc = (tid & 15) << 2;
    float acc[4][4] = {};

    for (int k0 = 0; k0 < K; k0 += 16) {
        float4 av = *(const float4*)(A + (size_t)(m0 + ar) * K + k0 + ak);
        As[ak + 0][ar] = av.x;
        As[ak + 1][ar] = av.y;
        As[ak + 2][ar] = av.z;
        As[ak + 3][ar] = av.w;
        *(float4*)&Bs[wr][wc] = *(const float4*)(W + (size_t)(k0 + wr) * N + n0 + wc);
        __syncthreads();
#pragma unroll
        for (int kk = 0; kk < 16; ++kk) {
            float4 a = *(const float4*)&As[kk][tr];
            float4 bv = *(const float4*)&Bs[kk][tc];
            acc[0][0] += a.x * bv.x; acc[0][1] += a.x * bv.y; acc[0][2] += a.x * bv.z; acc[0][3] += a.x * bv.w;
            acc[1][0] += a.y * bv.x; acc[1][1] += a.y * bv.y; acc[1][2] += a.y * bv.z; acc[1][3] += a.y * bv.w;
            acc[2][0] += a.z * bv.x; acc[2][1] += a.z * bv.y; acc[2][2] += a.z * bv.z; acc[2][3] += a.z * bv.w;
            acc[3][0] += a.w * bv.x; acc[3][1] += a.w * bv.y; acc[3][2] += a.w * bv.z; acc[3][3] += a.w * bv.w;
        }
        __syncthreads();
    }
    float4 bb = *(const float4*)(bias + n0 + tc);
#pragma unroll
    for (int u = 0; u < 4; ++u) {
        float4 o = make_float4(acc[u][0] + bb.x, acc[u][1] + bb.y, acc[u][2] + bb.z, acc[u][3] + bb.w);
        *(float4*)(Cout + (size_t)(m0 + tr + u) * N + n0 + tc) = o;
    }
}

// ---------------- tf32 tensor-core GEMM: C = A @ W + bias, fused L/R via blockIdx.z ----------------
template <int BM, int BN, int WM, int WN>
__global__ __launch_bounds__(256) void gemm_tf32(const float* __restrict__ A,
                                                 const float* __restrict__ W0,
                                                 const float* __restrict__ bi0,
                                                 const float* __restrict__ W1,
                                                 const float* __restrict__ bi1,
                                                 float* __restrict__ C0,
                                                 float* __restrict__ C1,
                                                 int M, int N, int K) {
    constexpr int WARPS_M = BM / WM;
    constexpr int MT = WM / 16;
    constexpr int NT = WN / 8;
    constexpr int SA = BM + 8;
    constexpr int SB = BN + 8;
    __shared__ __align__(16) unsigned As[16 * SA];
    __shared__ __align__(16) unsigned Bs[16 * SB];

    const float* W = blockIdx.z ? W1 : W0;
    const float* bi = blockIdx.z ? bi1 : bi0;
    float* C = blockIdx.z ? C1 : C0;

    int tid = threadIdx.x;
    int m0 = blockIdx.x * BM, n0 = blockIdx.y * BN;
    int w = tid >> 5, lane = tid & 31;
    int gid = lane >> 2, tig = lane & 3;
    int wm0 = (w % WARPS_M) * WM;
    int wn0 = (w / WARPS_M) * WN;
    float acc[MT][NT][4] = {};

    for (int k0 = 0; k0 < K; k0 += 16) {
        if (BM == 64) {
            int row = tid >> 2, kq = (tid & 3) * 4;
            float4 v = *(const float4*)(A + (size_t)(m0 + row) * K + k0 + kq);
            As[(kq + 0) * SA + row] = f2tf(v.x);
            As[(kq + 1) * SA + row] = f2tf(v.y);
            As[(kq + 2) * SA + row] = f2tf(v.z);
            As[(kq + 3) * SA + row] = f2tf(v.w);
        } else {
            int row = tid >> 3, kq = (tid & 7) * 2;
            float2 v = *(const float2*)(A + (size_t)(m0 + row) * K + k0 + kq);
            As[(kq + 0) * SA + row] = f2tf(v.x);
            As[(kq + 1) * SA + row] = f2tf(v.y);
        }
#pragma unroll
        for (int l = 0; l < (BN * 16) / 1024; ++l) {
            int idx = tid + l * 256;
            int k = idx / (BN / 4), nq = (idx % (BN / 4)) * 4;
            float4 v = *(const float4*)(W + (size_t)(k0 + k) * N + n0 + nq);
            uint4 u = make_uint4(f2tf(v.x), f2tf(v.y), f2tf(v.z), f2tf(v.w));
            *(uint4*)&Bs[k * SB + nq] = u;
        }
        __syncthreads();
#pragma unroll
        for (int ks = 0; ks < 16; ks += 8) {
            unsigned af[MT][4], bf[NT][2];
#pragma unroll
            for (int mt = 0; mt < MT; ++mt) {
                int m = wm0 + mt * 16 + gid;
                af[mt][0] = As[(ks + tig) * SA + m];
                af[mt][1] = As[(ks + tig) * SA + m + 8];
                af[mt][2] = As[(ks + tig + 4) * SA + m];
                af[mt][3] = As[(ks + tig + 4) * SA + m + 8];
            }
#pragma unroll
            for (int nt = 0; nt < NT; ++nt) {
                int n = wn0 + nt * 8 + gid;
                bf[nt][0] = Bs[(ks + tig) * SB + n];
                bf[nt][1] = Bs[(ks + tig + 4) * SB + n];
            }
#pragma unroll
            for (int mt = 0; mt < MT; ++mt)
#pragma unroll
                for (int nt = 0; nt < NT; ++nt) mma_tf32(acc[mt][nt], af[mt], bf[nt]);
        }
        __syncthreads();
    }
#pragma unroll
    for (int mt = 0; mt < MT; ++mt) {
        int r = m0 + wm0 + mt * 16 + gid;
#pragma unroll
        for (int nt = 0; nt < NT; ++nt) {
            int c = n0 + wn0 + nt * 8 + tig * 2;
            float bv0 = bi[c], bv1 = bi[c + 1];
            *(float2*)(C + (size_t)r * N + c) = make_float2(acc[mt][nt][0] + bv0, acc[mt][nt][1] + bv1);
            *(float2*)(C + (size_t)(r + 8) * N + c) = make_float2(acc[mt][nt][2] + bv0, acc[mt][nt][3] + bv1);
        }
    }
}

// ---------------- fused multi-head GATv2 attention with neighbor compaction ----------------
template <int H, int C, bool SELF, bool POOL>
__global__ __launch_bounds__(H * C) void gat_attn_c(const float* __restrict__ xl,
                                                    const float* __restrict__ xr,
                                                    const float* __restrict__ att,
                                                    const float* __restrict__ adjp,
                                                    const float* __restrict__ thrp,
                                                    const float* __restrict__ bias,
                                                    float* __restrict__ out) {
    constexpr int HC = H * C;
    constexpr int NWARP = HC / 32;
    constexpr int WPH = NWARP / H;
    constexpr int NG = C / 128;
    __shared__ __align__(16) float xr_s[HC];
    __shared__ __align__(16) float att_s[HC];
    __shared__ float e_s[H][104];
    __shared__ int nbr[NR];
    __shared__ int s_cnt;
    int i = blockIdx.x, b = blockIdx.y;
    int tid = threadIdx.x, lane = tid & 31, w = tid >> 5;
    int node = b * NR + i;
    xr_s[tid] = xr[(size_t)node * HC + tid];
    att_s[tid] = att[tid];
    float thrb = thrp[b];
    const float* adjrow = adjp + b * FLATN + i * NR;

    if (w == 0) {
        int cnt = 0;
#pragma unroll
        for (int base = 0; base < 128; base += 32) {
            int j = base + lane;
            bool m = (j < NR) && ((adjrow[j] > thrb) || (SELF && j == i));
            unsigned bal = __ballot_sync(0xFFFFFFFFu, m);
            int pos = cnt + __popc(bal & ((1u << lane) - 1u));
            if (m) nbr[pos] = j;
            cnt += __popc(bal);
        }
        if (lane == 0) s_cnt = cnt;
    }
    __syncthreads();
    int cnt = s_cnt;

    {
        int h = w / WPH, jw = w % WPH;
        const float* xrh = xr_s + h * C;
        const float* ath = att_s + h * C;
        for (int s = jw; s < cnt; s += WPH) {
            int j = nbr[s];
            const float* xlj = xl + (size_t)(b * NR + j) * HC + h * C;
            float p = 0.f;
#pragma unroll
            for (int g = 0; g < NG; ++g) {
                int c = g * 128 + lane * 4;
                float4 xv = *(const float4*)(xlj + c);
                float4 rv = *(const float4*)(xrh + c);
                float4 avv = *(const float4*)(ath + c);
                float s0 = xv.x + rv.x; s0 = (s0 > 0.f) ? s0 : 0.2f * s0; p += s0 * avv.x;
                float s1 = xv.y + rv.y; s1 = (s1 > 0.f) ? s1 : 0.2f * s1; p += s1 * avv.y;
                float s2 = xv.z + rv.z; s2 = (s2 > 0.f) ? s2 : 0.2f * s2; p += s2 * avv.z;
                float s3 = xv.w + rv.w; s3 = (s3 > 0.f) ? s3 : 0.2f * s3; p += s3 * avv.w;
            }
#pragma unroll
            for (int off = 16; off > 0; off >>= 1) p += __shfl_xor_sync(0xffffffffu, p, off);
            if (lane == 0) e_s[h][s] = p;
        }
    }
    __syncthreads();

    if (w < H && cnt > 0) {
        float mx = -3.0e38f;
        for (int s = lane; s < cnt; s += 32) mx = fmaxf(mx, e_s[w][s]);
#pragma unroll
        for (int off = 16; off > 0; off >>= 1) mx = fmaxf(mx, __shfl_xor_sync(0xffffffffu, mx, off));
        float se = 0.f;
        for (int s = lane; s < cnt; s += 32) {
            float t = expf(e_s[w][s] - mx);
            e_s[w][s] = t;
            se += t;
        }
#pragma unroll
        for (int off = 16; off > 0; off >>= 1) se += __shfl_xor_sync(0xffffffffu, se, off);
        float inv = 1.f / se;
        for (int s = lane; s < cnt; s += 32) e_s[w][s] *= inv;
    }
    __syncthreads();

    int hh = tid / C;
    float acc = 0.f;
    const float* xlb = xl + (size_t)(b * NR) * HC + tid;
    int s = 0;
    for (; s + 4 <= cnt; s += 4) {
        float a0 = e_s[hh][s + 0], a1 = e_s[hh][s + 1];
        float a2 = e_s[hh][s + 2], a3 = e_s[hh][s + 3];
        int j0 = nbr[s + 0], j1 = nbr[s + 1], j2 = nbr[s + 2], j3 = nbr[s + 3];
        float v0 = xlb[(size_t)j0 * HC];
        float v1 = xlb[(size_t)j1 * HC];
        float v2 = xlb[(size_t)j2 * HC];
        float v3 = xlb[(size_t)j3 * HC];
        acc += a0 * v0;
        acc += a1 * v1;
        acc += a2 * v2;
        acc += a3 * v3;
    }
    for (; s < cnt; ++s) acc += e_s[hh][s] * xlb[(size_t)nbr[s] * HC];
    float o = geluf(acc + bias[tid]);
    if (POOL) {
        atomicAdd(&out[b * HC + tid], o * 0.01f);
    } else {
        out[(size_t)node * HC + tid] = o;
    }
}

// ---------------- host launcher ----------------
extern "C" void kernel_launch(void* const* d_in, const int* in_sizes, int n_in,
                              void* d_out, int out_size) {
    (void)in_sizes; (void)n_in; (void)out_size;
    const float* raw   = (const float*)d_in[0];
    const float* gbW   = (const float*)d_in[1];
    const float* gbb   = (const float*)d_in[2];
    const float* feW1  = (const float*)d_in[3];
    const float* feb1  = (const float*)d_in[4];
    const float* feW2  = (const float*)d_in[5];
    const float* feb2  = (const float*)d_in[6];
    const float* feg   = (const float*)d_in[7];
    const float* febet = (const float*)d_in[8];
    const float* Wl1   = (const float*)d_in[9];
    const float* bl1   = (const float*)d_in[10];
    const float* Wr1   = (const float*)d_in[11];
    const float* br1   = (const float*)d_in[12];
    const float* att1  = (const float*)d_in[13];
    const float* bias1 = (const float*)d_in[14];
    const float* Wl2   = (const float*)d_in[15];
    const float* bl2   = (const float*)d_in[16];
    const float* Wr2   = (const float*)d_in[17];
    const float* br2   = (const float*)d_in[18];
    const float* att2  = (const float*)d_in[19];
    const float* bias2 = (const float*)d_in[20];
    const float* Wl3   = (const float*)d_in[21];
    const float* bl3   = (const float*)d_in[22];
    const float* Wr3   = (const float*)d_in[23];
    const float* br3   = (const float*)d_in[24];
    const float* att3  = (const float*)d_in[25];
    const float* bias3 = (const float*)d_in[26];

    float *adj, *thr, *x0, *xl1, *xr1, *h1, *xl2, *xr2, *h2, *xl3, *xr3;
    cudaGetSymbolAddress((void**)&adj, g_adj);
    cudaGetSymbolAddress((void**)&thr, g_thr);
    cudaGetSymbolAddress((void**)&x0, g_x0);
    cudaGetSymbolAddress((void**)&xl1, g_xl1);
    cudaGetSymbolAddress((void**)&xr1, g_xr1);
    cudaGetSymbolAddress((void**)&h1, g_h1);
    cudaGetSymbolAddress((void**)&xl2, g_xl2);
    cudaGetSymbolAddress((void**)&xr2, g_xr2);
    cudaGetSymbolAddress((void**)&h2, g_h2);
    cudaGetSymbolAddress((void**)&xl3, g_xl3);
    cudaGetSymbolAddress((void**)&xr3, g_xr3);

    // 1) graph-builder GEMM (cp.async 4-stage pipeline, split-K x25)
    gemm1_v6<<<dim3(79, G1_KC), 256>>>(raw, gbW);
    // 2) fused zsum + adjacency + stats + FE + quantile (+ d_out zeroing)
    cudaFuncSetAttribute(fused_stats_quant, cudaFuncAttributeMaxDynamicSharedMemorySize,
                         2 * FLATN * (int)sizeof(float));
    fused_stats_quant<<<BB, 1024, 2 * FLATN * sizeof(float)>>>(
        gbb, feW1, feb1, feW2, feb2, feg, febet, (float*)d_out);
    // 3) GAT layer 1 (no self-loops), fused fp32 K=16 linears
    gemm_tiled2<<<dim3(25, 16, 2), 256>>>(x0, Wl1, bl1, Wr1, br1, xl1, xr1, 1600, 1024, 16);
    gat_attn_c<8, 128, false, false><<<dim3(NR, BB), 1024>>>(xl1, xr1, att1, adj, thr, bias1, h1);
    // 4) GAT layer 2 (self-loops)
    gemm_tf32<64, 128, 32, 32><<<dim3(25, 8, 2), 256>>>(h1, Wl2, bl2, Wr2, br2, xl2, xr2, 1600, 1024, 1024);
    gat_attn_c<4, 256, true, false><<<dim3(NR, BB), 1024>>>(xl2, xr2, att2, adj, thr, bias2, h2);
    // 5) GAT layer 3 (self-loops, H=1) + fused mean pool into d_out
    gemm_tf32<32, 128, 32, 16><<<dim3(50, 1, 2), 256>>>(h2, Wl3, bl3, Wr3, br3, xl3, xr3, 1600, 128, 1024);
    gat_attn_c<1, 128, true, true><<<dim3(NR, BB), 128>>>(xl3, xr3, att3, adj, thr, bias3, (float*)d_out);
}

// round 16
// speedup vs baseline: 1.5083x; 1.0363x over previous
#include <cuda_runtime.h>
#include <cuda_bf16.h>
#include <math.h>
#include <float.h>

#define NR 100
#define BB 16
#define FLATN 10000
#define G1_KC 25
#define G1_CH 400
#define G1_S 4

// ---------------- scratch (device globals; no allocations) ----------------
__device__ __align__(128) float g_Z8[G1_KC][BB * FLATN];
__device__ __align__(128) float g_adj[BB * FLATN];
__device__ float g_thr[BB];
__device__ __align__(128) float g_x0[BB * NR * 16];
__device__ __align__(128) float g_xl1[BB * NR * 1024];
__device__ __align__(128) float g_xr1[BB * NR * 1024];
__device__ __align__(128) float g_h1[BB * NR * 1024];
__device__ __align__(128) float g_xl2[BB * NR * 1024];
__device__ __align__(128) float g_xr2[BB * NR * 1024];
__device__ __align__(128) float g_h2[BB * NR * 1024];
__device__ __align__(128) float g_xl3[BB * NR * 128];
__device__ __align__(128) float g_xr3[BB * NR * 128];

__device__ __forceinline__ float sigm(float x) { return 1.f / (1.f + expf(-x)); }
__device__ __forceinline__ float geluf(float x) { return 0.5f * x * (1.f + erff(x * 0.70710678118654752f)); }
__device__ __forceinline__ unsigned f2tf(float x) {
    unsigned u;
    asm("cvt.rna.tf32.f32 %0, %1;" : "=r"(u) : "f"(x));
    return u;
}
__device__ __forceinline__ void mma_tf32(float* d, const unsigned* a, const unsigned* b) {
    asm volatile(
        "mma.sync.aligned.m16n8k8.row.col.f32.tf32.tf32.f32 "
        "{%0,%1,%2,%3},{%4,%5,%6,%7},{%8,%9},{%0,%1,%2,%3};\n"
        : "+f"(d[0]), "+f"(d[1]), "+f"(d[2]), "+f"(d[3])
        : "r"(a[0]), "r"(a[1]), "r"(a[2]), "r"(a[3]), "r"(b[0]), "r"(b[1]));
}
__device__ __forceinline__ void mma_bf16(float* d, const unsigned* a, const unsigned* b) {
    asm volatile(
        "mma.sync.aligned.m16n8k16.row.col.f32.bf16.bf16.f32 "
        "{%0,%1,%2,%3},{%4,%5,%6,%7},{%8,%9},{%0,%1,%2,%3};\n"
        : "+f"(d[0]), "+f"(d[1]), "+f"(d[2]), "+f"(d[3])
        : "r"(a[0]), "r"(a[1]), "r"(a[2]), "r"(a[3]), "r"(b[0]), "r"(b[1]));
}
__device__ __forceinline__ unsigned pack_bf(float x, float y) {
    __nv_bfloat162 t = __floats2bfloat162_rn(x, y);
    return *(unsigned*)&t;
}
__device__ __forceinline__ void hilo2(float x, float y, unsigned& hi, unsigned& lo) {
    float hx = __bfloat162float(__float2bfloat16(x));
    float hy = __bfloat162float(__float2bfloat16(y));
    hi = pack_bf(x, y);
    lo = pack_bf(x - hx, y - hy);
}

// ---------------- GEMM1 v6: 4-stage cp.async pipeline, consumer-side bf16 hi/lo ----------------
__global__ __launch_bounds__(256) void gemm1_v6(const float* __restrict__ A,
                                                const float* __restrict__ W) {
    constexpr int WST = 132;
    constexpr int AST = 20;
    __shared__ __align__(16) float Wb[G1_S][16 * WST];
    __shared__ __align__(16) float Ab[G1_S][16 * AST];
    int tid = threadIdx.x;
    int n0 = blockIdx.x * 128;
    int kc = blockIdx.y;
    int kbeg = kc * G1_CH;
    int w = tid >> 5, lane = tid & 31, gid = lane >> 2, tig = lane & 3;
    int wn0 = w * 16;
    float acc[2][4] = {};

    auto issue = [&](int step, int buf) {
        int k0 = kbeg + step * 16;
#pragma unroll
        for (int l = 0; l < 2; ++l) {
            int c = tid + l * 256;
            int row = c >> 5, col = (c & 31) * 4;
            int gn = n0 + col;
            const float* src = W + (size_t)(k0 + row) * FLATN + ((gn + 4 <= FLATN) ? gn : 0);
            int sz = (gn + 4 <= FLATN) ? 16 : 0;
            unsigned dst = (unsigned)__cvta_generic_to_shared(&Wb[buf][row * WST + col]);
            asm volatile("cp.async.cg.shared.global [%0], [%1], 16, %2;\n"
                         :: "r"(dst), "l"(src), "r"(sz));
        }
        if (tid < 128) {
            int m = tid >> 3, cc = (tid & 7) * 2;
            const float* src = A + (size_t)m * FLATN + k0 + cc;
            unsigned dst = (unsigned)__cvta_generic_to_shared(&Ab[buf][m * AST + cc]);
            asm volatile("cp.async.ca.shared.global [%0], [%1], 8;\n" :: "r"(dst), "l"(src));
        }
        asm volatile("cp.async.commit_group;\n");
    };

    const int NSTEP = G1_CH / 16;  // 25
#pragma unroll
    for (int s = 0; s < G1_S - 1; ++s) issue(s, s);

    for (int s = 0; s < NSTEP; ++s) {
        asm volatile("cp.async.wait_group %0;\n" :: "n"(G1_S - 2));
        __syncthreads();
        int nb = s + G1_S - 1;
        if (nb < NSTEP) issue(nb, nb & 3);
        else asm volatile("cp.async.commit_group;\n");

        const float* Wc = Wb[s & 3];
        const float* Ac = Ab[s & 3];
        unsigned ah[4], al[4];
        {
            float2 p00 = *(const float2*)&Ac[gid * AST + 2 * tig];
            float2 p10 = *(const float2*)&Ac[(gid + 8) * AST + 2 * tig];
            float2 p01 = *(const float2*)&Ac[gid * AST + 2 * tig + 8];
            float2 p11 = *(const float2*)&Ac[(gid + 8) * AST + 2 * tig + 8];
            hilo2(p00.x, p00.y, ah[0], al[0]);
            hilo2(p10.x, p10.y, ah[1], al[1]);
            hilo2(p01.x, p01.y, ah[2], al[2]);
            hilo2(p11.x, p11.y, ah[3], al[3]);
        }
#pragma unroll
        for (int nf = 0; nf < 2; ++nf) {
            int n = wn0 + nf * 8 + gid;
            float w00 = Wc[(2 * tig) * WST + n];
            float w01 = Wc[(2 * tig + 1) * WST + n];
            float w10 = Wc[(2 * tig + 8) * WST + n];
            float w11 = Wc[(2 * tig + 9) * WST + n];
            unsigned bh[2], bl[2];
            hilo2(w00, w01, bh[0], bl[0]);
            hilo2(w10, w11, bh[1], bl[1]);
            mma_bf16(acc[nf], ah, bh);
            mma_bf16(acc[nf], ah, bl);
            mma_bf16(acc[nf], al, bh);
        }
    }
#pragma unroll
    for (int nf = 0; nf < 2; ++nf) {
        int col = n0 + wn0 + nf * 8 + tig * 2;
        if (col < FLATN) {
            float* Z = g_Z8[kc];
            *(float2*)(Z + gid * FLATN + col) = make_float2(acc[nf][0], acc[nf][1]);
            *(float2*)(Z + (gid + 8) * FLATN + col) = make_float2(acc[nf][2], acc[nf][3]);
        }
    }
}

// ---------------- FUSED: zsum + adjacency + row stats + FE MLP/LN + quantile ----------------
__global__ __launch_bounds__(1024) void fused_stats_quant(const float* __restrict__ gbb,
                                                          const float* __restrict__ W1,
                                                          const float* __restrict__ b1,
                                                          const float* __restrict__ W2,
                                                          const float* __restrict__ b2,
                                                          const float* __restrict__ gam,
                                                          const float* __restrict__ beta,
                                                          float* __restrict__ outp) {
    extern __shared__ float smem[];
    float* zs = smem;
    float* adjs = smem + FLATN;
    __shared__ unsigned hist[256];
    __shared__ float m_s[NR], s_s[NR];
    __shared__ unsigned s_prefix, s_rank;
    __shared__ unsigned redc[32], redm[32];
    int b = blockIdx.x, tid = threadIdx.x, lane = tid & 31, w = tid >> 5;
    if (tid < 128) outp[b * 128 + tid] = 0.f;

    for (int idx = tid; idx < FLATN; idx += 1024) {
        float s = gbb[idx];
#pragma unroll
        for (int c = 0; c < G1_KC; ++c) s += g_Z8[c][b * FLATN + idx];
        zs[idx] = s;
    }
    __syncthreads();

    for (int idx = tid; idx < FLATN; idx += 1024) {
        int i = idx / NR, j = idx - i * NR;
        float a = 0.5f * (sigm(zs[idx]) + sigm(zs[j * NR + i]));
        adjs[idx] = a;
        g_adj[b * FLATN + idx] = a;
    }
    __syncthreads();

    for (int r = w; r < NR; r += 32) {
        const float* row = adjs + r * NR;
        float v0 = row[lane];
        float v1 = row[lane + 32];
        float v2 = row[lane + 64];
        float v3 = (lane < 4) ? row[lane + 96] : 0.f;
        float su = v0 + v1 + v2 + v3;
#pragma unroll
        for (int off = 16; off > 0; off >>= 1) su += __shfl_xor_sync(0xFFFFFFFFu, su, off);
        float mean = su * 0.01f;
        float d0 = v0 - mean, d1 = v1 - mean, d2 = v2 - mean;
        float d3 = (lane < 4) ? (v3 - mean) : 0.f;
        float sq = d0 * d0 + d1 * d1 + d2 * d2 + d3 * d3;
#pragma unroll
        for (int off = 16; off > 0; off >>= 1) sq += __shfl_xor_sync(0xFFFFFFFFu, sq, off);
        if (lane == 0) {
            m_s[r] = mean;
            s_s[r] = sqrtf(fmaxf(sq * (1.f / 99.f), 0.f)) + 1e-6f;
        }
    }
    __syncthreads();

    for (int t = tid; t < NR * 16; t += 1024) {
        int r = t >> 4, ch = t & 15;
        float m = m_s[r], s = s_s[r];
        float acc = b2[ch];
#pragma unroll
        for (int hh = 0; hh < 8; ++hh) {
            float tt = m * W1[hh] + s * W1[8 + hh] + b1[hh];
            acc += geluf(tt) * W2[hh * 16 + ch];
        }
        float mu = acc;
#pragma unroll
        for (int off = 8; off > 0; off >>= 1) mu += __shfl_xor_sync(0xFFFFFFFFu, mu, off, 16);
        mu *= (1.f / 16.f);
        float d = acc - mu;
        float vv = d * d;
#pragma unroll
        for (int off = 8; off > 0; off >>= 1) vv += __shfl_xor_sync(0xFFFFFFFFu, vv, off, 16);
        vv *= (1.f / 16.f);
        g_x0[(b * NR + r) * 16 + ch] = d / sqrtf(vv + 1e-5f) * gam[ch] + beta[ch];
    }
    __syncthreads();

    unsigned rank = 7499;
    unsigned prefix = 0, pmask = 0;
#pragma unroll
    for (int byte = 3; byte >= 0; --byte) {
        int shift = byte * 8;
        if (tid < 256) hist[tid] = 0;
        __syncthreads();
        for (int base = 0; base < FLATN; base += 1024) {
            int i = base + tid;
            bool valid = i < FLATN;
            unsigned v = valid ? __float_as_uint(adjs[i]) : 0u;
            bool take = valid && ((v & pmask) == prefix);
            unsigned bin = (v >> shift) & 255u;
            unsigned key = take ? bin : 0xFFFFFFFFu;
            unsigned peers = __match_any_sync(0xFFFFFFFFu, key);
            if (take && ((unsigned)(__ffs(peers) - 1) == (unsigned)lane))
                atomicAdd(&hist[bin], __popc(peers));
        }
        __syncthreads();
        if (tid < 32) {
            unsigned base8 = tid * 8;
            unsigned loc = 0;
#pragma unroll
            for (int t = 0; t < 8; ++t) loc += hist[base8 + t];
            unsigned inc = loc;
#pragma unroll
            for (int off = 1; off < 32; off <<= 1) {
                unsigned v = __shfl_up_sync(0xFFFFFFFFu, inc, off);
                if (lane >= off) inc += v;
            }
            unsigned exc = inc - loc;
            if (rank >= exc && rank < exc + loc) {
                unsigned cum = exc, t = base8;
                while (cum + hist[t] <= rank) { cum += hist[t]; ++t; }
                s_prefix = prefix | (t << shift);
                s_rank = rank - cum;
            }
        }
        __syncthreads();
        prefix = s_prefix;
        rank = s_rank;
        pmask |= 0xFFu << shift;
        __syncthreads();
    }
    unsigned v0b = prefix;

    unsigned cle = 0, mab = 0xFFFFFFFFu;
    for (int i = tid; i < FLATN; i += 1024) {
        unsigned v = __float_as_uint(adjs[i]);
        if (v <= v0b) ++cle;
        else mab = min(mab, v);
    }
#pragma unroll
    for (int off = 16; off > 0; off >>= 1) {
        cle += __shfl_xor_sync(0xFFFFFFFFu, cle, off);
        mab = min(mab, __shfl_xor_sync(0xFFFFFFFFu, mab, off));
    }
    if (lane == 0) { redc[w] = cle; redm[w] = mab; }
    __syncthreads();
    if (tid == 0) {
        unsigned tc = 0, tm = 0xFFFFFFFFu;
        for (int t = 0; t < 32; ++t) { tc += redc[t]; tm = min(tm, redm[t]); }
        unsigned v1b = (tc >= 7501u) ? v0b : tm;
        float v0 = __uint_as_float(v0b), v1 = __uint_as_float(v1b);
        g_thr[b] = v0 + 0.25f * (v1 - v0);
    }
}

// ---------------- fp32 tiled GEMM, fused L/R via blockIdx.z (K=16 layer-1 linears) ----------------
__global__ __launch_bounds__(256) void gemm_tiled2(const float* __restrict__ A,
                                                   const float* __restrict__ W0,
                                                   const float* __restrict__ bi0,
                                                   const float* __restrict__ W1,
                                                   const float* __restrict__ bi1,
                                                   float* __restrict__ C0,
                                                   float* __restrict__ C1,
                                                   int M, int N, int K) {
    __shared__ __align__(16) float As[16][68];
    __shared__ __align__(16) float Bs[16][68];
    const float* W = blockIdx.z ? W1 : W0;
    const float* bias = blockIdx.z ? bi1 : bi0;
    float* Cout = blockIdx.z ? C1 : C0;
    int tid = threadIdx.x;
    int m0 = blockIdx.x * 64, n0 = blockIdx.y * 64;
    int ar = tid >> 2, ak = (tid & 3) << 2;
    int wr = tid >> 4, wc = (tid & 15) << 2;
    int tr = (tid >> 4) << 2, tc = (tid & 15) << 2;
    float acc[4][4] = {};

    for (int k0 = 0; k0 < K; k0 += 16) {
        float4 av = *(const float4*)(A + (size_t)(m0 + ar) * K + k0 + ak);
        As[ak + 0][ar] = av.x;
        As[ak + 1][ar] = av.y;
        As[ak + 2][ar] = av.z;
        As[ak + 3][ar] = av.w;
        *(float4*)&Bs[wr][wc] = *(const float4*)(W + (size_t)(k0 + wr) * N + n0 + wc);
        __syncthreads();
#pragma unroll
        for (int kk = 0; kk < 16; ++kk) {
            float4 a = *(const float4*)&As[kk][tr];
            float4 bv = *(const float4*)&Bs[kk][tc];
            acc[0][0] += a.x * bv.x; acc[0][1] += a.x * bv.y; acc[0][2] += a.x * bv.z; acc[0][3] += a.x * bv.w;
            acc[1][0] += a.y * bv.x; acc[1][1] += a.y * bv.y; acc[1][2] += a.y * bv.z; acc[1][3] += a.y * bv.w;
            acc[2][0] += a.z * bv.x; acc[2][1] += a.z * bv.y; acc[2][2] += a.z * bv.z; acc[2][3] += a.z * bv.w;
            acc[3][0] += a.w * bv.x; acc[3][1] += a.w * bv.y; acc[3][2] += a.w * bv.z; acc[3][3] += a.w * bv.w;
        }
        __syncthreads();
    }
    float4 bb = *(const float4*)(bias + n0 + tc);
#pragma unroll
    for (int u = 0; u < 4; ++u) {
        float4 o = make_float4(acc[u][0] + bb.x, acc[u][1] + bb.y, acc[u][2] + bb.z, acc[u][3] + bb.w);
        *(float4*)(Cout + (size_t)(m0 + tr + u) * N + n0 + tc) = o;
    }
}

// ---------------- tf32 tensor-core GEMM: C = A @ W + bias, fused L/R via blockIdx.z ----------------
template <int BM, int BN, int WM, int WN>
__global__ __launch_bounds__(256) void gemm_tf32(const float* __restrict__ A,
                                                 const float* __restrict__ W0,
                                                 const float* __restrict__ bi0,
                                                 const float* __restrict__ W1,
                                                 const float* __restrict__ bi1,
                                                 float* __restrict__ C0,
                                                 float* __restrict__ C1,
                                                 int M, int N, int K) {
    constexpr int WARPS_M = BM / WM;
    constexpr int MT = WM / 16;
    constexpr int NT = WN / 8;
    constexpr int SA = BM + 8;
    constexpr int SB = BN + 8;
    __shared__ __align__(16) unsigned As[16 * SA];
    __shared__ __align__(16) unsigned Bs[16 * SB];

    const float* W = blockIdx.z ? W1 : W0;
    const float* bi = blockIdx.z ? bi1 : bi0;
    float* C = blockIdx.z ? C1 : C0;

    int tid = threadIdx.x;
    int m0 = blockIdx.x * BM, n0 = blockIdx.y * BN;
    int w = tid >> 5, lane = tid & 31;
    int gid = lane >> 2, tig = lane & 3;
    int wm0 = (w % WARPS_M) * WM;
    int wn0 = (w / WARPS_M) * WN;
    float acc[MT][NT][4] = {};

    for (int k0 = 0; k0 < K; k0 += 16) {
        if (BM == 64) {
            int row = tid >> 2, kq = (tid & 3) * 4;
            float4 v = *(const float4*)(A + (size_t)(m0 + row) * K + k0 + kq);
            As[(kq + 0) * SA + row] = f2tf(v.x);
            As[(kq + 1) * SA + row] = f2tf(v.y);
            As[(kq + 2) * SA + row] = f2tf(v.z);
            As[(kq + 3) * SA + row] = f2tf(v.w);
        } else {
            int row = tid >> 3, kq = (tid & 7) * 2;
            float2 v = *(const float2*)(A + (size_t)(m0 + row) * K + k0 + kq);
            As[(kq + 0) * SA + row] = f2tf(v.x);
            As[(kq + 1) * SA + row] = f2tf(v.y);
        }
#pragma unroll
        for (int l = 0; l < (BN * 16) / 1024; ++l) {
            int idx = tid + l * 256;
            int k = idx / (BN / 4), nq = (idx % (BN / 4)) * 4;
            float4 v = *(const float4*)(W + (size_t)(k0 + k) * N + n0 + nq);
            uint4 u = make_uint4(f2tf(v.x), f2tf(v.y), f2tf(v.z), f2tf(v.w));
            *(uint4*)&Bs[k * SB + nq] = u;
        }
        __syncthreads();
#pragma unroll
        for (int ks = 0; ks < 16; ks += 8) {
            unsigned af[MT][4], bf[NT][2];
#pragma unroll
            for (int mt = 0; mt < MT; ++mt) {
                int m = wm0 + mt * 16 + gid;
                af[mt][0] = As[(ks + tig) * SA + m];
                af[mt][1] = As[(ks + tig) * SA + m + 8];
                af[mt][2] = As[(ks + tig + 4) * SA + m];
                af[mt][3] = As[(ks + tig + 4) * SA + m + 8];
            }
#pragma unroll
            for (int nt = 0; nt < NT; ++nt) {
                int n = wn0 + nt * 8 + gid;
                bf[nt][0] = Bs[(ks + tig) * SB + n];
                bf[nt][1] = Bs[(ks + tig + 4) * SB + n];
            }
#pragma unroll
            for (int mt = 0; mt < MT; ++mt)
#pragma unroll
                for (int nt = 0; nt < NT; ++nt) mma_tf32(acc[mt][nt], af[mt], bf[nt]);
        }
        __syncthreads();
    }
#pragma unroll
    for (int mt = 0; mt < MT; ++mt) {
        int r = m0 + wm0 + mt * 16 + gid;
#pragma unroll
        for (int nt = 0; nt < NT; ++nt) {
            int c = n0 + wn0 + nt * 8 + tig * 2;
            float bv0 = bi[c], bv1 = bi[c + 1];
            *(float2*)(C + (size_t)r * N + c) = make_float2(acc[mt][nt][0] + bv0, acc[mt][nt][1] + bv1);
            *(float2*)(C + (size_t)(r + 8) * N + c) = make_float2(acc[mt][nt][2] + bv0, acc[mt][nt][3] + bv1);
        }
    }
}

// ---------------- fused multi-head GATv2 attention, 2-way ILP score phase ----------------
template <int H, int C, bool SELF, bool POOL>
__global__ __launch_bounds__(H * C) void gat_attn_c(const float* __restrict__ xl,
                                                    const float* __restrict__ xr,
                                                    const float* __restrict__ att,
                                                    const float* __restrict__ adjp,
                                                    const float* __restrict__ thrp,
                                                    const float* __restrict__ bias,
                                                    float* __restrict__ out) {
    constexpr int HC = H * C;
    constexpr int NWARP = HC / 32;
    constexpr int WPH = NWARP / H;
    constexpr int NG = C / 128;
    __shared__ __align__(16) float xr_s[HC];
    __shared__ __align__(16) float att_s[HC];
    __shared__ float e_s[H][104];
    __shared__ int nbr[NR];
    __shared__ int s_cnt;
    int i = blockIdx.x, b = blockIdx.y;
    int tid = threadIdx.x, lane = tid & 31, w = tid >> 5;
    int node = b * NR + i;
    xr_s[tid] = xr[(size_t)node * HC + tid];
    att_s[tid] = att[tid];
    float thrb = thrp[b];
    const float* adjrow = adjp + b * FLATN + i * NR;

    if (w == 0) {
        int cnt = 0;
#pragma unroll
        for (int base = 0; base < 128; base += 32) {
            int j = base + lane;
            bool m = (j < NR) && ((adjrow[j] > thrb) || (SELF && j == i));
            unsigned bal = __ballot_sync(0xFFFFFFFFu, m);
            int pos = cnt + __popc(bal & ((1u << lane) - 1u));
            if (m) nbr[pos] = j;
            cnt += __popc(bal);
        }
        if (lane == 0) s_cnt = cnt;
    }
    __syncthreads();
    int cnt = s_cnt;

    // scores over compacted list, 2 rows per warp iteration (independent chains)
    {
        int h = w / WPH, jw = w % WPH;
        const float* xrh = xr_s + h * C;
        const float* ath = att_s + h * C;
        const float* xlh = xl + (size_t)(b * NR) * HC + h * C;
        for (int s = jw; s < cnt; s += 2 * WPH) {
            int s1 = s + WPH;
            bool has1 = s1 < cnt;
            int j0 = nbr[s];
            int j1 = has1 ? nbr[s1] : j0;
            const float* xl0 = xlh + (size_t)j0 * HC;
            const float* xl1p = xlh + (size_t)j1 * HC;
            float p0 = 0.f, p1 = 0.f;
#pragma unroll
            for (int g = 0; g < NG; ++g) {
                int c = g * 128 + lane * 4;
                float4 xv0 = *(const float4*)(xl0 + c);
                float4 xv1 = *(const float4*)(xl1p + c);
                float4 rv = *(const float4*)(xrh + c);
                float4 avv = *(const float4*)(ath + c);
                float t;
                t = xv0.x + rv.x; t = (t > 0.f) ? t : 0.2f * t; p0 += t * avv.x;
                t = xv1.x + rv.x; t = (t > 0.f) ? t : 0.2f * t; p1 += t * avv.x;
                t = xv0.y + rv.y; t = (t > 0.f) ? t : 0.2f * t; p0 += t * avv.y;
                t = xv1.y + rv.y; t = (t > 0.f) ? t : 0.2f * t; p1 += t * avv.y;
                t = xv0.z + rv.z; t = (t > 0.f) ? t : 0.2f * t; p0 += t * avv.z;
                t = xv1.z + rv.z; t = (t > 0.f) ? t : 0.2f * t; p1 += t * avv.z;
                t = xv0.w + rv.w; t = (t > 0.f) ? t : 0.2f * t; p0 += t * avv.w;
                t = xv1.w + rv.w; t = (t > 0.f) ? t : 0.2f * t; p1 += t * avv.w;
            }
#pragma unroll
            for (int off = 16; off > 0; off >>= 1) {
                p0 += __shfl_xor_sync(0xffffffffu, p0, off);
                p1 += __shfl_xor_sync(0xffffffffu, p1, off);
            }
            if (lane == 0) {
                e_s[h][s] = p0;
                if (has1) e_s[h][s1] = p1;
            }
        }
    }
    __syncthreads();

    if (w < H && cnt > 0) {
        float mx = -3.0e38f;
        for (int s = lane; s < cnt; s += 32) mx = fmaxf(mx, e_s[w][s]);
#pragma unroll
        for (int off = 16; off > 0; off >>= 1) mx = fmaxf(mx, __shfl_xor_sync(0xffffffffu, mx, off));
        float se = 0.f;
        for (int s = lane; s < cnt; s += 32) {
            float t = expf(e_s[w][s] - mx);
            e_s[w][s] = t;
            se += t;
        }
#pragma unroll
        for (int off = 16; off > 0; off >>= 1) se += __shfl_xor_sync(0xffffffffu, se, off);
        float inv = 1.f / se;
        for (int s = lane; s < cnt; s += 32) e_s[w][s] *= inv;
    }
    __syncthreads();

    int hh = tid / C;
    float acc = 0.f;
    const float* xlb = xl + (size_t)(b * NR) * HC + tid;
    int s = 0;
    for (; s + 4 <= cnt; s += 4) {
        float a0 = e_s[hh][s + 0], a1 = e_s[hh][s + 1];
        float a2 = e_s[hh][s + 2], a3 = e_s[hh][s + 3];
        int j0 = nbr[s + 0], j1 = nbr[s + 1], j2 = nbr[s + 2], j3 = nbr[s + 3];
        float v0 = xlb[(size_t)j0 * HC];
        float v1 = xlb[(size_t)j1 * HC];
        float v2 = xlb[(size_t)j2 * HC];
        float v3 = xlb[(size_t)j3 * HC];
        acc += a0 * v0;
        acc += a1 * v1;
        acc += a2 * v2;
        acc += a3 * v3;
    }
    for (; s < cnt; ++s) acc += e_s[hh][s] * xlb[(size_t)nbr[s] * HC];
    float o = geluf(acc + bias[tid]);
    if (POOL) {
        atomicAdd(&out[b * HC + tid], o * 0.01f);
    } else {
        out[(size_t)node * HC + tid] = o;
    }
}

// ---------------- host launcher ----------------
extern "C" void kernel_launch(void* const* d_in, const int* in_sizes, int n_in,
                              void* d_out, int out_size) {
    (void)in_sizes; (void)n_in; (void)out_size;
    const float* raw   = (const float*)d_in[0];
    const float* gbW   = (const float*)d_in[1];
    const float* gbb   = (const float*)d_in[2];
    const float* feW1  = (const float*)d_in[3];
    const float* feb1  = (const float*)d_in[4];
    const float* feW2  = (const float*)d_in[5];
    const float* feb2  = (const float*)d_in[6];
    const float* feg   = (const float*)d_in[7];
    const float* febet = (const float*)d_in[8];
    const float* Wl1   = (const float*)d_in[9];
    const float* bl1   = (const float*)d_in[10];
    const float* Wr1   = (const float*)d_in[11];
    const float* br1   = (const float*)d_in[12];
    const float* att1  = (const float*)d_in[13];
    const float* bias1 = (const float*)d_in[14];
    const float* Wl2   = (const float*)d_in[15];
    const float* bl2   = (const float*)d_in[16];
    const float* Wr2   = (const float*)d_in[17];
    const float* br2   = (const float*)d_in[18];
    const float* att2  = (const float*)d_in[19];
    const float* bias2 = (const float*)d_in[20];
    const float* Wl3   = (const float*)d_in[21];
    const float* bl3   = (const float*)d_in[22];
    const float* Wr3   = (const float*)d_in[23];
    const float* br3   = (const float*)d_in[24];
    const float* att3  = (const float*)d_in[25];
    const float* bias3 = (const float*)d_in[26];

    float *adj, *thr, *x0, *xl1, *xr1, *h1, *xl2, *xr2, *h2, *xl3, *xr3;
    cudaGetSymbolAddress((void**)&adj, g_adj);
    cudaGetSymbolAddress((void**)&thr, g_thr);
    cudaGetSymbolAddress((void**)&x0, g_x0);
    cudaGetSymbolAddress((void**)&xl1, g_xl1);
    cudaGetSymbolAddress((void**)&xr1, g_xr1);
    cudaGetSymbolAddress((void**)&h1, g_h1);
    cudaGetSymbolAddress((void**)&xl2, g_xl2);
    cudaGetSymbolAddress((void**)&xr2, g_xr2);
    cudaGetSymbolAddress((void**)&h2, g_h2);
    cudaGetSymbolAddress((void**)&xl3, g_xl3);
    cudaGetSymbolAddress((void**)&xr3, g_xr3);

    // 1) graph-builder GEMM (cp.async 4-stage pipeline, split-K x25)
    gemm1_v6<<<dim3(79, G1_KC), 256>>>(raw, gbW);
    // 2) fused zsum + adjacency + stats + FE + quantile (+ d_out zeroing)
    cudaFuncSetAttribute(fused_stats_quant, cudaFuncAttributeMaxDynamicSharedMemorySize,
                         2 * FLATN * (int)sizeof(float));
    fused_stats_quant<<<BB, 1024, 2 * FLATN * sizeof(float)>>>(
        gbb, feW1, feb1, feW2, feb2, feg, febet, (float*)d_out);
    // 3) GAT layer 1 (no self-loops), fused fp32 K=16 linears
    gemm_tiled2<<<dim3(25, 16, 2), 256>>>(x0, Wl1, bl1, Wr1, br1, xl1, xr1, 1600, 1024, 16);
    gat_attn_c<8, 128, false, false><<<dim3(NR, BB), 1024>>>(xl1, xr1, att1, adj, thr, bias1, h1);
    // 4) GAT layer 2 (self-loops)
    gemm_tf32<64, 128, 32, 32><<<dim3(25, 8, 2), 256>>>(h1, Wl2, bl2, Wr2, br2, xl2, xr2, 1600, 1024, 1024);
    gat_attn_c<4, 256, true, false><<<dim3(NR, BB), 1024>>>(xl2, xr2, att2, adj, thr, bias2, h2);
    // 5) GAT layer 3 (self-loops, H=1) + fused mean pool into d_out
    gemm_tf32<32, 128, 32, 16><<<dim3(50, 1, 2), 256>>>(h2, Wl3, bl3, Wr3, br3, xl3, xr3, 1600, 128, 1024);
    gat_attn_c<1, 128, true, true><<<dim3(NR, BB), 128>>>(xl3, xr3, att3, adj, thr, bias3, (float*)d_out);
}